// round 1
// baseline (speedup 1.0000x reference)
#include <cuda_runtime.h>
#include <math.h>

#define S_LEN 2048
#define B_SZ 2
#define D_MODEL 1024
#define NH 16
#define HD 64
#define M_ROWS (B_SZ * S_LEN)   // 4096
#define QKV_COLS (3 * D_MODEL)  // 3072

// Scratch: qkv activations [4096, 3072] and attention output z [4096, 1024]
__device__ float g_qkv[(size_t)M_ROWS * QKV_COLS];
__device__ float g_z[(size_t)M_ROWS * D_MODEL];

// ---------------------------------------------------------------------------
// GEMM: C[M,N] = A[M,K] @ W[K,N] + bias[N]
// 128x128 tile, 256 threads, 8x8 per thread (split 2x2 of 4x4 for conflict-free
// smem reads), BK=8. fp32 throughout.
// ---------------------------------------------------------------------------
__global__ __launch_bounds__(256, 2) void gemm_bias_kernel(
    const float* __restrict__ A, const float* __restrict__ W,
    const float* __restrict__ bias, float* __restrict__ C,
    int M, int N, int K)
{
    __shared__ float As[8][132];   // [k][m], pad for conflict-free transposed store
    __shared__ float Bs[8][132];   // [k][n]

    const int t  = threadIdx.x;
    const int tx = t & 15;
    const int ty = t >> 4;
    const int m0 = blockIdx.y << 7;
    const int n0 = blockIdx.x << 7;

    float acc[8][8];
#pragma unroll
    for (int i = 0; i < 8; i++)
#pragma unroll
        for (int j = 0; j < 8; j++) acc[i][j] = 0.f;

    const int arow = t >> 1;           // 0..127
    const int acol = (t & 1) << 2;     // 0 or 4
    const int brow = t >> 5;           // 0..7
    const int bcol = (t & 31) << 2;    // 0..124

    const float* Aptr = A + (size_t)(m0 + arow) * K + acol;
    const float* Wptr = W + (size_t)brow * N + n0 + bcol;

    for (int k0 = 0; k0 < K; k0 += 8) {
        float4 av = *(const float4*)(Aptr + k0);
        float4 bv = *(const float4*)(Wptr + (size_t)k0 * N);
        As[acol + 0][arow] = av.x;
        As[acol + 1][arow] = av.y;
        As[acol + 2][arow] = av.z;
        As[acol + 3][arow] = av.w;
        *(float4*)&Bs[brow][bcol] = bv;
        __syncthreads();

#pragma unroll
        for (int kk = 0; kk < 8; kk++) {
            float4 a0 = *(const float4*)&As[kk][ty << 2];
            float4 a1 = *(const float4*)&As[kk][64 + (ty << 2)];
            float4 b0 = *(const float4*)&Bs[kk][tx << 2];
            float4 b1 = *(const float4*)&Bs[kk][64 + (tx << 2)];
            float a[8] = {a0.x, a0.y, a0.z, a0.w, a1.x, a1.y, a1.z, a1.w};
            float b[8] = {b0.x, b0.y, b0.z, b0.w, b1.x, b1.y, b1.z, b1.w};
#pragma unroll
            for (int i = 0; i < 8; i++)
#pragma unroll
                for (int j = 0; j < 8; j++) acc[i][j] += a[i] * b[j];
        }
        __syncthreads();
    }

    // Epilogue: add bias, store
#pragma unroll
    for (int ih = 0; ih < 2; ih++) {
#pragma unroll
        for (int i = 0; i < 4; i++) {
            int r = m0 + ih * 64 + (ty << 2) + i;
#pragma unroll
            for (int jh = 0; jh < 2; jh++) {
                int c = n0 + jh * 64 + (tx << 2);
                float4 bb = *(const float4*)(bias + c);
                float4 v;
                v.x = acc[ih * 4 + i][jh * 4 + 0] + bb.x;
                v.y = acc[ih * 4 + i][jh * 4 + 1] + bb.y;
                v.z = acc[ih * 4 + i][jh * 4 + 2] + bb.z;
                v.w = acc[ih * 4 + i][jh * 4 + 3] + bb.w;
                *(float4*)(C + (size_t)r * N + c) = v;
            }
        }
    }
}

// ---------------------------------------------------------------------------
// Flash attention (causal), fp32. One block = one (q-tile of 64, b*h).
// Bq=Bk=64, 256 threads, 4x4 fragments. K tile stored XOR-swizzled so the
// S = Q K^T inner loop reads are 2-phase (optimal).
// qkv layout per row m=b*S+s: [q(0..1023) | k(1024..2047) | v(2048..3071)],
// head h occupies cols h*64..h*64+63 within each third.
// Output z: [B,S,H*hd] row-major (== transpose(0,2,1,3).reshape).
// ---------------------------------------------------------------------------
#define ATT_SMEM_FLOATS (4096 * 3 + 64 * 68 + 192)
#define ATT_SMEM_BYTES  (ATT_SMEM_FLOATS * 4)

__global__ __launch_bounds__(256) void attn_kernel(
    const float* __restrict__ qkv, float* __restrict__ z)
{
    extern __shared__ float sm[];
    float* Qs   = sm;                 // [64][64] plain
    float* Ks   = Qs + 4096;          // [64][64] swizzled: group g of row c at g^(c>>2)
    float* Vs   = Ks + 4096;          // [64][64] plain
    float* Ss   = Vs + 4096;          // [64][68] padded (softmax scan conflicts)
    float* mrow = Ss + 64 * 68;       // [64]
    float* lrow = mrow + 64;          // [64]
    float* alph = lrow + 64;          // [64]

    const int t  = threadIdx.x;
    const int qt = blockIdx.x;        // 0..31
    const int bh = blockIdx.y;        // 0..31
    const int b  = bh >> 4;
    const int h  = bh & 15;
    const int tx = t & 15;
    const int ty = t >> 4;
    const int r0 = ty << 2;
    const int c0 = tx << 2;

    const size_t rs = QKV_COLS;  // 3072
    const float* qbase = qkv + (size_t)(b * S_LEN + qt * 64) * rs + h * HD;

    // Load Q tile (once)
#pragma unroll
    for (int i = 0; i < 4; i++) {
        int idx = i * 256 + t;
        int r = idx >> 4, g = idx & 15;
        float4 v = *(const float4*)(qbase + (size_t)r * rs + (g << 2));
        *(float4*)&Qs[(r << 6) + (g << 2)] = v;
    }
    if (t < 64) { mrow[t] = -1e30f; lrow[t] = 0.f; }

    float o[4][4];
#pragma unroll
    for (int i = 0; i < 4; i++)
#pragma unroll
        for (int j = 0; j < 4; j++) o[i][j] = 0.f;

    for (int kt = 0; kt <= qt; kt++) {
        // Load K (swizzled) and V tiles
        const float* kbase = qkv + (size_t)(b * S_LEN + kt * 64) * rs + D_MODEL + h * HD;
        const float* vbase = kbase + D_MODEL;
#pragma unroll
        for (int i = 0; i < 4; i++) {
            int idx = i * 256 + t;
            int c = idx >> 4, g = idx & 15;
            float4 kv = *(const float4*)(kbase + (size_t)c * rs + (g << 2));
            *(float4*)&Ks[(c << 6) + (((g ^ (c >> 2)) & 15) << 2)] = kv;
            float4 vv = *(const float4*)(vbase + (size_t)c * rs + (g << 2));
            *(float4*)&Vs[(c << 6) + (g << 2)] = vv;
        }
        __syncthreads();

        // S = Q K^T (4x4 fragment per thread)
        float s[4][4];
#pragma unroll
        for (int i = 0; i < 4; i++)
#pragma unroll
            for (int j = 0; j < 4; j++) s[i][j] = 0.f;

#pragma unroll
        for (int g = 0; g < 16; g++) {
            float4 q4[4], k4[4];
#pragma unroll
            for (int i = 0; i < 4; i++)
                q4[i] = *(const float4*)&Qs[((r0 + i) << 6) + (g << 2)];
#pragma unroll
            for (int j = 0; j < 4; j++) {
                int c = c0 + j;
                k4[j] = *(const float4*)&Ks[(c << 6) + (((g ^ (c >> 2)) & 15) << 2)];
            }
#pragma unroll
            for (int i = 0; i < 4; i++)
#pragma unroll
                for (int j = 0; j < 4; j++) {
                    s[i][j] += q4[i].x * k4[j].x;
                    s[i][j] += q4[i].y * k4[j].y;
                    s[i][j] += q4[i].z * k4[j].z;
                    s[i][j] += q4[i].w * k4[j].w;
                }
        }

        const bool diag = (kt == qt);
#pragma unroll
        for (int i = 0; i < 4; i++) {
            float4 sv;
            float v0 = s[i][0] * 0.125f;
            float v1 = s[i][1] * 0.125f;
            float v2 = s[i][2] * 0.125f;
            float v3 = s[i][3] * 0.125f;
            if (diag) {
                int r = r0 + i;
                if (c0 + 0 > r) v0 = -1e30f;
                if (c0 + 1 > r) v1 = -1e30f;
                if (c0 + 2 > r) v2 = -1e30f;
                if (c0 + 3 > r) v3 = -1e30f;
            }
            sv.x = v0; sv.y = v1; sv.z = v2; sv.w = v3;
            *(float4*)&Ss[(r0 + i) * 68 + c0] = sv;
        }
        __syncthreads();

        // Online softmax: 4 threads per row, shuffle reduce within quad
        {
            const int r  = t >> 2;
            const int qq = t & 3;
            float* srow = &Ss[r * 68 + qq * 16];
            float4 v0 = *(float4*)&srow[0];
            float4 v1 = *(float4*)&srow[4];
            float4 v2 = *(float4*)&srow[8];
            float4 v3 = *(float4*)&srow[12];
            float mloc = fmaxf(fmaxf(fmaxf(v0.x, v0.y), fmaxf(v0.z, v0.w)),
                               fmaxf(fmaxf(v1.x, v1.y), fmaxf(v1.z, v1.w)));
            mloc = fmaxf(mloc, fmaxf(fmaxf(v2.x, v2.y), fmaxf(v2.z, v2.w)));
            mloc = fmaxf(mloc, fmaxf(fmaxf(v3.x, v3.y), fmaxf(v3.z, v3.w)));
            mloc = fmaxf(mloc, __shfl_xor_sync(0xffffffffu, mloc, 1));
            mloc = fmaxf(mloc, __shfl_xor_sync(0xffffffffu, mloc, 2));
            float mold = mrow[r];
            float mnew = fmaxf(mold, mloc);
            float lsum;
            {
                float4 p0, p1, p2, p3;
                p0.x = __expf(v0.x - mnew); p0.y = __expf(v0.y - mnew);
                p0.z = __expf(v0.z - mnew); p0.w = __expf(v0.w - mnew);
                p1.x = __expf(v1.x - mnew); p1.y = __expf(v1.y - mnew);
                p1.z = __expf(v1.z - mnew); p1.w = __expf(v1.w - mnew);
                p2.x = __expf(v2.x - mnew); p2.y = __expf(v2.y - mnew);
                p2.z = __expf(v2.z - mnew); p2.w = __expf(v2.w - mnew);
                p3.x = __expf(v3.x - mnew); p3.y = __expf(v3.y - mnew);
                p3.z = __expf(v3.z - mnew); p3.w = __expf(v3.w - mnew);
                *(float4*)&srow[0]  = p0;
                *(float4*)&srow[4]  = p1;
                *(float4*)&srow[8]  = p2;
                *(float4*)&srow[12] = p3;
                lsum = (p0.x + p0.y + p0.z + p0.w) + (p1.x + p1.y + p1.z + p1.w)
                     + (p2.x + p2.y + p2.z + p2.w) + (p3.x + p3.y + p3.z + p3.w);
            }
            lsum += __shfl_xor_sync(0xffffffffu, lsum, 1);
            lsum += __shfl_xor_sync(0xffffffffu, lsum, 2);
            if (qq == 0) {
                float alpha = __expf(mold - mnew);
                lrow[r] = lrow[r] * alpha + lsum;
                mrow[r] = mnew;
                alph[r] = alpha;
            }
        }
        __syncthreads();

        // O = O*alpha + P @ V
        {
            float al[4];
#pragma unroll
            for (int i = 0; i < 4; i++) al[i] = alph[r0 + i];
#pragma unroll
            for (int i = 0; i < 4; i++)
#pragma unroll
                for (int j = 0; j < 4; j++) o[i][j] *= al[i];

#pragma unroll
            for (int j2 = 0; j2 < 64; j2 += 4) {
                float pr[4][4];
#pragma unroll
                for (int i = 0; i < 4; i++) {
                    float4 p4 = *(const float4*)&Ss[(r0 + i) * 68 + j2];
                    pr[i][0] = p4.x; pr[i][1] = p4.y; pr[i][2] = p4.z; pr[i][3] = p4.w;
                }
#pragma unroll
                for (int u = 0; u < 4; u++) {
                    float4 v4 = *(const float4*)&Vs[((j2 + u) << 6) + c0];
#pragma unroll
                    for (int i = 0; i < 4; i++) {
                        float p = pr[i][u];
                        o[i][0] += p * v4.x;
                        o[i][1] += p * v4.y;
                        o[i][2] += p * v4.z;
                        o[i][3] += p * v4.w;
                    }
                }
            }
        }
        __syncthreads();
    }

    // Epilogue: O / l, write z[b, s, h*64 + c]
#pragma unroll
    for (int i = 0; i < 4; i++) {
        float linv = 1.f / lrow[r0 + i];
        int srow_g = qt * 64 + r0 + i;
        float4 v;
        v.x = o[i][0] * linv;
        v.y = o[i][1] * linv;
        v.z = o[i][2] * linv;
        v.w = o[i][3] * linv;
        *(float4*)(z + (size_t)(b * S_LEN + srow_g) * D_MODEL + h * HD + c0) = v;
    }
}

// ---------------------------------------------------------------------------
extern "C" void kernel_launch(void* const* d_in, const int* in_sizes, int n_in,
                              void* d_out, int out_size)
{
    const float* x     = (const float*)d_in[0];
    const float* w_qkv = (const float*)d_in[1];
    const float* b_qkv = (const float*)d_in[2];
    const float* w_out = (const float*)d_in[3];
    const float* b_out = (const float*)d_in[4];
    float* out = (float*)d_out;

    float* qkv_ptr = nullptr;
    float* z_ptr   = nullptr;
    cudaGetSymbolAddress((void**)&qkv_ptr, g_qkv);
    cudaGetSymbolAddress((void**)&z_ptr, g_z);

    cudaFuncSetAttribute(attn_kernel,
                         cudaFuncAttributeMaxDynamicSharedMemorySize,
                         ATT_SMEM_BYTES);

    // 1) QKV GEMM: [4096,1024] @ [1024,3072] + bias
    {
        dim3 grid(QKV_COLS / 128, M_ROWS / 128);
        gemm_bias_kernel<<<grid, 256>>>(x, w_qkv, b_qkv, qkv_ptr,
                                        M_ROWS, QKV_COLS, D_MODEL);
    }
    // 2) Causal flash attention per (q-tile, b*h)
    {
        dim3 grid(S_LEN / 64, B_SZ * NH);
        attn_kernel<<<grid, 256, ATT_SMEM_BYTES>>>(qkv_ptr, z_ptr);
    }
    // 3) Output GEMM: [4096,1024] @ [1024,1024] + bias
    {
        dim3 grid(D_MODEL / 128, M_ROWS / 128);
        gemm_bias_kernel<<<grid, 256>>>(z_ptr, w_out, b_out, out,
                                        M_ROWS, D_MODEL, D_MODEL);
    }
}

// round 3
// speedup vs baseline: 1.4899x; 1.4899x over previous
#include <cuda_runtime.h>
#include <cuda_bf16.h>
#include <math.h>

#define S_LEN 2048
#define B_SZ 2
#define D_MODEL 1024
#define NH 16
#define HD 64
#define M_ROWS (B_SZ * S_LEN)   // 4096
#define QKV_COLS (3 * D_MODEL)  // 3072

// Scratch: qkv activations [4096, 3072] and attention output z [4096, 1024]
__device__ float g_qkv[(size_t)M_ROWS * QKV_COLS];
__device__ float g_z[(size_t)M_ROWS * D_MODEL];

// ---------------------------------------------------------------------------
// bf16 helpers
// ---------------------------------------------------------------------------
__device__ __forceinline__ unsigned pack_bf2(float x, float y) {
    __nv_bfloat162 h = __floats2bfloat162_rn(x, y);
    return *reinterpret_cast<unsigned*>(&h);
}

__device__ __forceinline__ void mma_bf16(float* c,
                                         unsigned a0, unsigned a1,
                                         unsigned a2, unsigned a3,
                                         unsigned b0, unsigned b1) {
    asm volatile(
        "mma.sync.aligned.m16n8k16.row.col.f32.bf16.bf16.f32 "
        "{%0,%1,%2,%3}, {%4,%5,%6,%7}, {%8,%9}, {%0,%1,%2,%3};\n"
        : "+f"(c[0]), "+f"(c[1]), "+f"(c[2]), "+f"(c[3])
        : "r"(a0), "r"(a1), "r"(a2), "r"(a3), "r"(b0), "r"(b1));
}

__device__ __forceinline__ void ldsm_x4(unsigned r[4], unsigned addr) {
    asm volatile("ldmatrix.sync.aligned.m8n8.x4.shared.b16 {%0,%1,%2,%3}, [%4];"
                 : "=r"(r[0]), "=r"(r[1]), "=r"(r[2]), "=r"(r[3]) : "r"(addr));
}
__device__ __forceinline__ void ldsm_x2t(unsigned r[2], unsigned addr) {
    asm volatile("ldmatrix.sync.aligned.m8n8.x2.trans.shared.b16 {%0,%1}, [%2];"
                 : "=r"(r[0]), "=r"(r[1]) : "r"(addr));
}

// ---------------------------------------------------------------------------
// bf16-split tensor-core GEMM: C[M,N] = A[M,K] @ W[K,N] + bias[N]
// A = Ah + Al (bf16 split); C += Ah@Wh + Al@Wh + Ah@Wl (lo*lo dropped, ~2^-18)
// BM=128, BN=128, BK=32; 8 warps (2x4), warp tile 64x32 via m16n8k16.
// A fragments: ldmatrix.x4 from Ah/Al[m][k]; B fragments: ldmatrix.x2.trans
// from Wh/Wl[k][n]. Pitches chosen for conflict-free ldmatrix phases.
// ---------------------------------------------------------------------------
#define APITCH 40
#define WPITCH 136

__global__ __launch_bounds__(256) void gemm_bf16s_kernel(
    const float* __restrict__ A, const float* __restrict__ W,
    const float* __restrict__ bias, float* __restrict__ C,
    int M, int N, int K)
{
    __shared__ __nv_bfloat16 Ah[128][APITCH];
    __shared__ __nv_bfloat16 Al[128][APITCH];
    __shared__ __nv_bfloat16 Wh[32][WPITCH];
    __shared__ __nv_bfloat16 Wl[32][WPITCH];

    const int t    = threadIdx.x;
    const int lane = t & 31;
    const int warp = t >> 5;
    const int g    = lane >> 2;
    const int tig  = lane & 3;
    const int wm   = warp >> 2;   // 0..1
    const int wn   = warp & 3;    // 0..3
    const int m0   = blockIdx.y << 7;
    const int n0   = blockIdx.x << 7;

    float acc[4][4][4];
#pragma unroll
    for (int i = 0; i < 4; i++)
#pragma unroll
        for (int j = 0; j < 4; j++)
#pragma unroll
            for (int r = 0; r < 4; r++) acc[i][j][r] = 0.f;

    // A loader: row = t>>1 (0..127), k-half = (t&1)*16
    const int ar  = t >> 1;
    const int akh = (t & 1) << 4;
    const float* Aptr = A + (size_t)(m0 + ar) * K + akh;
    // W loader: k-row = t>>3 (0..31), n-chunk = (t&7)*16
    const int wkr = t >> 3;
    const int wnb = (t & 7) << 4;
    const float* Wptr = W + (size_t)wkr * N + n0 + wnb;

    const unsigned ah_b = (unsigned)__cvta_generic_to_shared(&Ah[0][0]);
    const unsigned al_b = (unsigned)__cvta_generic_to_shared(&Al[0][0]);
    const unsigned wh_b = (unsigned)__cvta_generic_to_shared(&Wh[0][0]);
    const unsigned wl_b = (unsigned)__cvta_generic_to_shared(&Wl[0][0]);

    float4 ra[4], rw[4];
#pragma unroll
    for (int j = 0; j < 4; j++) {
        ra[j] = *(const float4*)(Aptr + 4 * j);
        rw[j] = *(const float4*)(Wptr + 4 * j);
    }

    for (int k0 = 0; k0 < K; k0 += 32) {
        // split + store A slab (16 k-values per thread)
#pragma unroll
        for (int j = 0; j < 4; j++) {
            float xs[4] = {ra[j].x, ra[j].y, ra[j].z, ra[j].w};
            float hi[4], lo[4];
#pragma unroll
            for (int e = 0; e < 4; e++) {
                __nv_bfloat16 h = __float2bfloat16_rn(xs[e]);
                hi[e] = __bfloat162float(h);
                lo[e] = xs[e] - hi[e];
            }
            *reinterpret_cast<unsigned*>(&Ah[ar][akh + 4 * j])     = pack_bf2(hi[0], hi[1]);
            *reinterpret_cast<unsigned*>(&Ah[ar][akh + 4 * j + 2]) = pack_bf2(hi[2], hi[3]);
            *reinterpret_cast<unsigned*>(&Al[ar][akh + 4 * j])     = pack_bf2(lo[0], lo[1]);
            *reinterpret_cast<unsigned*>(&Al[ar][akh + 4 * j + 2]) = pack_bf2(lo[2], lo[3]);
        }
        // split + store W slab (16 n-values per thread)
#pragma unroll
        for (int j = 0; j < 4; j++) {
            float xs[4] = {rw[j].x, rw[j].y, rw[j].z, rw[j].w};
            float hi[4], lo[4];
#pragma unroll
            for (int e = 0; e < 4; e++) {
                __nv_bfloat16 h = __float2bfloat16_rn(xs[e]);
                hi[e] = __bfloat162float(h);
                lo[e] = xs[e] - hi[e];
            }
            *reinterpret_cast<unsigned*>(&Wh[wkr][wnb + 4 * j])     = pack_bf2(hi[0], hi[1]);
            *reinterpret_cast<unsigned*>(&Wh[wkr][wnb + 4 * j + 2]) = pack_bf2(hi[2], hi[3]);
            *reinterpret_cast<unsigned*>(&Wl[wkr][wnb + 4 * j])     = pack_bf2(lo[0], lo[1]);
            *reinterpret_cast<unsigned*>(&Wl[wkr][wnb + 4 * j + 2]) = pack_bf2(lo[2], lo[3]);
        }
        __syncthreads();

        // prefetch next slab
        if (k0 + 32 < K) {
#pragma unroll
            for (int j = 0; j < 4; j++) {
                ra[j] = *(const float4*)(Aptr + k0 + 32 + 4 * j);
                rw[j] = *(const float4*)(Wptr + (size_t)(k0 + 32) * N + 4 * j);
            }
        }

#pragma unroll
        for (int kc = 0; kc < 32; kc += 16) {
            unsigned ahi[4][4], alo[4][4];
#pragma unroll
            for (int mt = 0; mt < 4; mt++) {
                const int row = (wm << 6) + (mt << 4) + (lane & 15);
                const int col = kc + ((lane >> 4) << 3);
                const unsigned off = (unsigned)(row * (APITCH * 2) + col * 2);
                ldsm_x4(ahi[mt], ah_b + off);
                ldsm_x4(alo[mt], al_b + off);
            }
#pragma unroll
            for (int nt = 0; nt < 4; nt++) {
                const int krow = kc + (lane & 15);
                const int ncol = (wn << 5) + (nt << 3);
                const unsigned off = (unsigned)(krow * (WPITCH * 2) + ncol * 2);
                unsigned bh[2], bl[2];
                ldsm_x2t(bh, wh_b + off);
                ldsm_x2t(bl, wl_b + off);
#pragma unroll
                for (int mt = 0; mt < 4; mt++) {
                    mma_bf16(acc[mt][nt], ahi[mt][0], ahi[mt][1], ahi[mt][2], ahi[mt][3], bh[0], bh[1]);
                    mma_bf16(acc[mt][nt], alo[mt][0], alo[mt][1], alo[mt][2], alo[mt][3], bh[0], bh[1]);
                    mma_bf16(acc[mt][nt], ahi[mt][0], ahi[mt][1], ahi[mt][2], ahi[mt][3], bl[0], bl[1]);
                }
            }
        }
        __syncthreads();
    }

    // Epilogue: bias + store. C fragment: c0=(g,2tig) c1=(g,2tig+1) c2/c3 at +8 rows.
#pragma unroll
    for (int mt = 0; mt < 4; mt++) {
        const int row0 = m0 + (wm << 6) + (mt << 4) + g;
        const int row1 = row0 + 8;
#pragma unroll
        for (int nt = 0; nt < 4; nt++) {
            const int col = n0 + (wn << 5) + (nt << 3) + (tig << 1);
            const float b0 = bias[col];
            const float b1 = bias[col + 1];
            float2 v0, v1;
            v0.x = acc[mt][nt][0] + b0; v0.y = acc[mt][nt][1] + b1;
            v1.x = acc[mt][nt][2] + b0; v1.y = acc[mt][nt][3] + b1;
            *(float2*)(C + (size_t)row0 * N + col) = v0;
            *(float2*)(C + (size_t)row1 * N + col) = v1;
        }
    }
}

// ---------------------------------------------------------------------------
// Flash attention (causal), fp32 — unchanged (known correct from round 1).
// ---------------------------------------------------------------------------
#define ATT_SMEM_FLOATS (4096 * 3 + 64 * 68 + 192)
#define ATT_SMEM_BYTES  (ATT_SMEM_FLOATS * 4)

__global__ __launch_bounds__(256) void attn_kernel(
    const float* __restrict__ qkv, float* __restrict__ z)
{
    extern __shared__ float sm[];
    float* Qs   = sm;
    float* Ks   = Qs + 4096;
    float* Vs   = Ks + 4096;
    float* Ss   = Vs + 4096;
    float* mrow = Ss + 64 * 68;
    float* lrow = mrow + 64;
    float* alph = lrow + 64;

    const int t  = threadIdx.x;
    const int qt = blockIdx.x;
    const int bh = blockIdx.y;
    const int b  = bh >> 4;
    const int h  = bh & 15;
    const int tx = t & 15;
    const int ty = t >> 4;
    const int r0 = ty << 2;
    const int c0 = tx << 2;

    const size_t rs = QKV_COLS;
    const float* qbase = qkv + (size_t)(b * S_LEN + qt * 64) * rs + h * HD;

#pragma unroll
    for (int i = 0; i < 4; i++) {
        int idx = i * 256 + t;
        int r = idx >> 4, gq = idx & 15;
        float4 v = *(const float4*)(qbase + (size_t)r * rs + (gq << 2));
        *(float4*)&Qs[(r << 6) + (gq << 2)] = v;
    }
    if (t < 64) { mrow[t] = -1e30f; lrow[t] = 0.f; }

    float o[4][4];
#pragma unroll
    for (int i = 0; i < 4; i++)
#pragma unroll
        for (int j = 0; j < 4; j++) o[i][j] = 0.f;

    for (int kt = 0; kt <= qt; kt++) {
        const float* kbase = qkv + (size_t)(b * S_LEN + kt * 64) * rs + D_MODEL + h * HD;
        const float* vbase = kbase + D_MODEL;
#pragma unroll
        for (int i = 0; i < 4; i++) {
            int idx = i * 256 + t;
            int c = idx >> 4, gq = idx & 15;
            float4 kv = *(const float4*)(kbase + (size_t)c * rs + (gq << 2));
            *(float4*)&Ks[(c << 6) + (((gq ^ (c >> 2)) & 15) << 2)] = kv;
            float4 vv = *(const float4*)(vbase + (size_t)c * rs + (gq << 2));
            *(float4*)&Vs[(c << 6) + (gq << 2)] = vv;
        }
        __syncthreads();

        float s[4][4];
#pragma unroll
        for (int i = 0; i < 4; i++)
#pragma unroll
            for (int j = 0; j < 4; j++) s[i][j] = 0.f;

#pragma unroll
        for (int gq = 0; gq < 16; gq++) {
            float4 q4[4], k4[4];
#pragma unroll
            for (int i = 0; i < 4; i++)
                q4[i] = *(const float4*)&Qs[((r0 + i) << 6) + (gq << 2)];
#pragma unroll
            for (int j = 0; j < 4; j++) {
                int c = c0 + j;
                k4[j] = *(const float4*)&Ks[(c << 6) + (((gq ^ (c >> 2)) & 15) << 2)];
            }
#pragma unroll
            for (int i = 0; i < 4; i++)
#pragma unroll
                for (int j = 0; j < 4; j++) {
                    s[i][j] += q4[i].x * k4[j].x;
                    s[i][j] += q4[i].y * k4[j].y;
                    s[i][j] += q4[i].z * k4[j].z;
                    s[i][j] += q4[i].w * k4[j].w;
                }
        }

        const bool diag = (kt == qt);
#pragma unroll
        for (int i = 0; i < 4; i++) {
            float4 sv;
            float v0 = s[i][0] * 0.125f;
            float v1 = s[i][1] * 0.125f;
            float v2 = s[i][2] * 0.125f;
            float v3 = s[i][3] * 0.125f;
            if (diag) {
                int r = r0 + i;
                if (c0 + 0 > r) v0 = -1e30f;
                if (c0 + 1 > r) v1 = -1e30f;
                if (c0 + 2 > r) v2 = -1e30f;
                if (c0 + 3 > r) v3 = -1e30f;
            }
            sv.x = v0; sv.y = v1; sv.z = v2; sv.w = v3;
            *(float4*)&Ss[(r0 + i) * 68 + c0] = sv;
        }
        __syncthreads();

        {
            const int r  = t >> 2;
            const int qq = t & 3;
            float* srow = &Ss[r * 68 + qq * 16];
            float4 v0 = *(float4*)&srow[0];
            float4 v1 = *(float4*)&srow[4];
            float4 v2 = *(float4*)&srow[8];
            float4 v3 = *(float4*)&srow[12];
            float mloc = fmaxf(fmaxf(fmaxf(v0.x, v0.y), fmaxf(v0.z, v0.w)),
                               fmaxf(fmaxf(v1.x, v1.y), fmaxf(v1.z, v1.w)));
            mloc = fmaxf(mloc, fmaxf(fmaxf(v2.x, v2.y), fmaxf(v2.z, v2.w)));
            mloc = fmaxf(mloc, fmaxf(fmaxf(v3.x, v3.y), fmaxf(v3.z, v3.w)));
            mloc = fmaxf(mloc, __shfl_xor_sync(0xffffffffu, mloc, 1));
            mloc = fmaxf(mloc, __shfl_xor_sync(0xffffffffu, mloc, 2));
            float mold = mrow[r];
            float mnew = fmaxf(mold, mloc);
            float lsum;
            {
                float4 p0, p1, p2, p3;
                p0.x = __expf(v0.x - mnew); p0.y = __expf(v0.y - mnew);
                p0.z = __expf(v0.z - mnew); p0.w = __expf(v0.w - mnew);
                p1.x = __expf(v1.x - mnew); p1.y = __expf(v1.y - mnew);
                p1.z = __expf(v1.z - mnew); p1.w = __expf(v1.w - mnew);
                p2.x = __expf(v2.x - mnew); p2.y = __expf(v2.y - mnew);
                p2.z = __expf(v2.z - mnew); p2.w = __expf(v2.w - mnew);
                p3.x = __expf(v3.x - mnew); p3.y = __expf(v3.y - mnew);
                p3.z = __expf(v3.z - mnew); p3.w = __expf(v3.w - mnew);
                *(float4*)&srow[0]  = p0;
                *(float4*)&srow[4]  = p1;
                *(float4*)&srow[8]  = p2;
                *(float4*)&srow[12] = p3;
                lsum = (p0.x + p0.y + p0.z + p0.w) + (p1.x + p1.y + p1.z + p1.w)
                     + (p2.x + p2.y + p2.z + p2.w) + (p3.x + p3.y + p3.z + p3.w);
            }
            lsum += __shfl_xor_sync(0xffffffffu, lsum, 1);
            lsum += __shfl_xor_sync(0xffffffffu, lsum, 2);
            if (qq == 0) {
                float alpha = __expf(mold - mnew);
                lrow[r] = lrow[r] * alpha + lsum;
                mrow[r] = mnew;
                alph[r] = alpha;
            }
        }
        __syncthreads();

        {
            float al[4];
#pragma unroll
            for (int i = 0; i < 4; i++) al[i] = alph[r0 + i];
#pragma unroll
            for (int i = 0; i < 4; i++)
#pragma unroll
                for (int j = 0; j < 4; j++) o[i][j] *= al[i];

#pragma unroll
            for (int j2 = 0; j2 < 64; j2 += 4) {
                float pr[4][4];
#pragma unroll
                for (int i = 0; i < 4; i++) {
                    float4 p4 = *(const float4*)&Ss[(r0 + i) * 68 + j2];
                    pr[i][0] = p4.x; pr[i][1] = p4.y; pr[i][2] = p4.z; pr[i][3] = p4.w;
                }
#pragma unroll
                for (int u = 0; u < 4; u++) {
                    float4 v4 = *(const float4*)&Vs[((j2 + u) << 6) + c0];
#pragma unroll
                    for (int i = 0; i < 4; i++) {
                        float p = pr[i][u];
                        o[i][0] += p * v4.x;
                        o[i][1] += p * v4.y;
                        o[i][2] += p * v4.z;
                        o[i][3] += p * v4.w;
                    }
                }
            }
        }
        __syncthreads();
    }

#pragma unroll
    for (int i = 0; i < 4; i++) {
        float linv = 1.f / lrow[r0 + i];
        int srow_g = qt * 64 + r0 + i;
        float4 v;
        v.x = o[i][0] * linv;
        v.y = o[i][1] * linv;
        v.z = o[i][2] * linv;
        v.w = o[i][3] * linv;
        *(float4*)(z + (size_t)(b * S_LEN + srow_g) * D_MODEL + h * HD + c0) = v;
    }
}

// ---------------------------------------------------------------------------
extern "C" void kernel_launch(void* const* d_in, const int* in_sizes, int n_in,
                              void* d_out, int out_size)
{
    const float* x     = (const float*)d_in[0];
    const float* w_qkv = (const float*)d_in[1];
    const float* b_qkv = (const float*)d_in[2];
    const float* w_out = (const float*)d_in[3];
    const float* b_out = (const float*)d_in[4];
    float* out = (float*)d_out;

    float* qkv_ptr = nullptr;
    float* z_ptr   = nullptr;
    cudaGetSymbolAddress((void**)&qkv_ptr, g_qkv);
    cudaGetSymbolAddress((void**)&z_ptr, g_z);

    cudaFuncSetAttribute(attn_kernel,
                         cudaFuncAttributeMaxDynamicSharedMemorySize,
                         ATT_SMEM_BYTES);

    // 1) QKV GEMM: [4096,1024] @ [1024,3072] + bias  (bf16-split tensor cores)
    {
        dim3 grid(QKV_COLS / 128, M_ROWS / 128);
        gemm_bf16s_kernel<<<grid, 256>>>(x, w_qkv, b_qkv, qkv_ptr,
                                         M_ROWS, QKV_COLS, D_MODEL);
    }
    // 2) Causal flash attention per (q-tile, b*h)
    {
        dim3 grid(S_LEN / 64, B_SZ * NH);
        attn_kernel<<<grid, 256, ATT_SMEM_BYTES>>>(qkv_ptr, z_ptr);
    }
    // 3) Output GEMM: [4096,1024] @ [1024,1024] + bias  (bf16-split tensor cores)
    {
        dim3 grid(D_MODEL / 128, M_ROWS / 128);
        gemm_bf16s_kernel<<<grid, 256>>>(z_ptr, w_out, b_out, out,
                                         M_ROWS, D_MODEL, D_MODEL);
    }
}

// round 5
// speedup vs baseline: 2.2768x; 1.5282x over previous
#include <cuda_runtime.h>
#include <cuda_bf16.h>
#include <math.h>

#define S_LEN 2048
#define B_SZ 2
#define D_MODEL 1024
#define NH 16
#define HD 64
#define M_ROWS (B_SZ * S_LEN)   // 4096
#define QKV_COLS (3 * D_MODEL)  // 3072

// Scratch: qkv activations [4096, 3072] and attention output z [4096, 1024]
__device__ float g_qkv[(size_t)M_ROWS * QKV_COLS];
__device__ float g_z[(size_t)M_ROWS * D_MODEL];

// ---------------------------------------------------------------------------
// bf16 / mma helpers
// ---------------------------------------------------------------------------
__device__ __forceinline__ unsigned pack_bf2(float x, float y) {
    __nv_bfloat162 h = __floats2bfloat162_rn(x, y);
    return *reinterpret_cast<unsigned*>(&h);
}

__device__ __forceinline__ void mma_bf16(float* c,
                                         unsigned a0, unsigned a1,
                                         unsigned a2, unsigned a3,
                                         unsigned b0, unsigned b1) {
    asm volatile(
        "mma.sync.aligned.m16n8k16.row.col.f32.bf16.bf16.f32 "
        "{%0,%1,%2,%3}, {%4,%5,%6,%7}, {%8,%9}, {%0,%1,%2,%3};\n"
        : "+f"(c[0]), "+f"(c[1]), "+f"(c[2]), "+f"(c[3])
        : "r"(a0), "r"(a1), "r"(a2), "r"(a3), "r"(b0), "r"(b1));
}

__device__ __forceinline__ void ldsm_x4(unsigned r[4], unsigned addr) {
    asm volatile("ldmatrix.sync.aligned.m8n8.x4.shared.b16 {%0,%1,%2,%3}, [%4];"
                 : "=r"(r[0]), "=r"(r[1]), "=r"(r[2]), "=r"(r[3]) : "r"(addr));
}
__device__ __forceinline__ void ldsm_x2(unsigned r[2], unsigned addr) {
    asm volatile("ldmatrix.sync.aligned.m8n8.x2.shared.b16 {%0,%1}, [%2];"
                 : "=r"(r[0]), "=r"(r[1]) : "r"(addr));
}
__device__ __forceinline__ void ldsm_x2t(unsigned r[2], unsigned addr) {
    asm volatile("ldmatrix.sync.aligned.m8n8.x2.trans.shared.b16 {%0,%1}, [%2];"
                 : "=r"(r[0]), "=r"(r[1]) : "r"(addr));
}

// split a float4 into hi/lo bf16x2 pairs
__device__ __forceinline__ void split4(float4 v,
                                       unsigned& h01, unsigned& h23,
                                       unsigned& l01, unsigned& l23) {
    float f[4] = {v.x, v.y, v.z, v.w};
    float hi[4], lo[4];
#pragma unroll
    for (int e = 0; e < 4; e++) {
        __nv_bfloat16 h = __float2bfloat16_rn(f[e]);
        hi[e] = __bfloat162float(h);
        lo[e] = f[e] - hi[e];
    }
    h01 = pack_bf2(hi[0], hi[1]); h23 = pack_bf2(hi[2], hi[3]);
    l01 = pack_bf2(lo[0], lo[1]); l23 = pack_bf2(lo[2], lo[3]);
}

// ---------------------------------------------------------------------------
// bf16-split tensor-core GEMM (unchanged from round 3, verified)
// ---------------------------------------------------------------------------
#define APITCH 40
#define WPITCH 136

__global__ __launch_bounds__(256) void gemm_bf16s_kernel(
    const float* __restrict__ A, const float* __restrict__ W,
    const float* __restrict__ bias, float* __restrict__ C,
    int M, int N, int K)
{
    __shared__ __nv_bfloat16 Ah[128][APITCH];
    __shared__ __nv_bfloat16 Al[128][APITCH];
    __shared__ __nv_bfloat16 Wh[32][WPITCH];
    __shared__ __nv_bfloat16 Wl[32][WPITCH];

    const int t    = threadIdx.x;
    const int lane = t & 31;
    const int warp = t >> 5;
    const int g    = lane >> 2;
    const int tig  = lane & 3;
    const int wm   = warp >> 2;
    const int wn   = warp & 3;
    const int m0   = blockIdx.y << 7;
    const int n0   = blockIdx.x << 7;

    float acc[4][4][4];
#pragma unroll
    for (int i = 0; i < 4; i++)
#pragma unroll
        for (int j = 0; j < 4; j++)
#pragma unroll
            for (int r = 0; r < 4; r++) acc[i][j][r] = 0.f;

    const int ar  = t >> 1;
    const int akh = (t & 1) << 4;
    const float* Aptr = A + (size_t)(m0 + ar) * K + akh;
    const int wkr = t >> 3;
    const int wnb = (t & 7) << 4;
    const float* Wptr = W + (size_t)wkr * N + n0 + wnb;

    const unsigned ah_b = (unsigned)__cvta_generic_to_shared(&Ah[0][0]);
    const unsigned al_b = (unsigned)__cvta_generic_to_shared(&Al[0][0]);
    const unsigned wh_b = (unsigned)__cvta_generic_to_shared(&Wh[0][0]);
    const unsigned wl_b = (unsigned)__cvta_generic_to_shared(&Wl[0][0]);

    float4 ra[4], rw[4];
#pragma unroll
    for (int j = 0; j < 4; j++) {
        ra[j] = *(const float4*)(Aptr + 4 * j);
        rw[j] = *(const float4*)(Wptr + 4 * j);
    }

    for (int k0 = 0; k0 < K; k0 += 32) {
#pragma unroll
        for (int j = 0; j < 4; j++) {
            unsigned h01, h23, l01, l23;
            split4(ra[j], h01, h23, l01, l23);
            *reinterpret_cast<unsigned*>(&Ah[ar][akh + 4 * j])     = h01;
            *reinterpret_cast<unsigned*>(&Ah[ar][akh + 4 * j + 2]) = h23;
            *reinterpret_cast<unsigned*>(&Al[ar][akh + 4 * j])     = l01;
            *reinterpret_cast<unsigned*>(&Al[ar][akh + 4 * j + 2]) = l23;
        }
#pragma unroll
        for (int j = 0; j < 4; j++) {
            unsigned h01, h23, l01, l23;
            split4(rw[j], h01, h23, l01, l23);
            *reinterpret_cast<unsigned*>(&Wh[wkr][wnb + 4 * j])     = h01;
            *reinterpret_cast<unsigned*>(&Wh[wkr][wnb + 4 * j + 2]) = h23;
            *reinterpret_cast<unsigned*>(&Wl[wkr][wnb + 4 * j])     = l01;
            *reinterpret_cast<unsigned*>(&Wl[wkr][wnb + 4 * j + 2]) = l23;
        }
        __syncthreads();

        if (k0 + 32 < K) {
#pragma unroll
            for (int j = 0; j < 4; j++) {
                ra[j] = *(const float4*)(Aptr + k0 + 32 + 4 * j);
                rw[j] = *(const float4*)(Wptr + (size_t)(k0 + 32) * N + 4 * j);
            }
        }

#pragma unroll
        for (int kc = 0; kc < 32; kc += 16) {
            unsigned ahi[4][4], alo[4][4];
#pragma unroll
            for (int mt = 0; mt < 4; mt++) {
                const int row = (wm << 6) + (mt << 4) + (lane & 15);
                const int col = kc + ((lane >> 4) << 3);
                const unsigned off = (unsigned)(row * (APITCH * 2) + col * 2);
                ldsm_x4(ahi[mt], ah_b + off);
                ldsm_x4(alo[mt], al_b + off);
            }
#pragma unroll
            for (int nt = 0; nt < 4; nt++) {
                const int krow = kc + (lane & 15);
                const int ncol = (wn << 5) + (nt << 3);
                const unsigned off = (unsigned)(krow * (WPITCH * 2) + ncol * 2);
                unsigned bh[2], bl[2];
                ldsm_x2t(bh, wh_b + off);
                ldsm_x2t(bl, wl_b + off);
#pragma unroll
                for (int mt = 0; mt < 4; mt++) {
                    mma_bf16(acc[mt][nt], ahi[mt][0], ahi[mt][1], ahi[mt][2], ahi[mt][3], bh[0], bh[1]);
                    mma_bf16(acc[mt][nt], alo[mt][0], alo[mt][1], alo[mt][2], alo[mt][3], bh[0], bh[1]);
                    mma_bf16(acc[mt][nt], ahi[mt][0], ahi[mt][1], ahi[mt][2], ahi[mt][3], bl[0], bl[1]);
                }
            }
        }
        __syncthreads();
    }

#pragma unroll
    for (int mt = 0; mt < 4; mt++) {
        const int row0 = m0 + (wm << 6) + (mt << 4) + g;
        const int row1 = row0 + 8;
#pragma unroll
        for (int nt = 0; nt < 4; nt++) {
            const int col = n0 + (wn << 5) + (nt << 3) + (tig << 1);
            const float b0 = bias[col];
            const float b1 = bias[col + 1];
            float2 v0, v1;
            v0.x = acc[mt][nt][0] + b0; v0.y = acc[mt][nt][1] + b1;
            v1.x = acc[mt][nt][2] + b0; v1.y = acc[mt][nt][3] + b1;
            *(float2*)(C + (size_t)row0 * N + col) = v0;
            *(float2*)(C + (size_t)row1 * N + col) = v1;
        }
    }
}

// ---------------------------------------------------------------------------
// Flash attention (causal) with bf16-split tensor-core MMAs.
// One block = (q-tile 64, b*h). 256 threads = 8 warps, warp tile m16 x n32
// (wm = warp>>1 in 0..3 -> m-slab; wn = warp&1 -> n-slab).
// S = Q K^T via 3-term split mma; fp32 softmax (staged in smem, unchanged
// logic); P emitted as split bf16; O += P V via 3-term split mma.
// Q/P stored [m][k] (ldsm .x4); K stored [n][k] (ldsm .x2 non-trans);
// V stored [k][n] (ldsm .x2.trans).
// ---------------------------------------------------------------------------
#define QP 72   // bf16 pitch (144B -> conflict-free ldmatrix row phases)
#define ATT2_SMEM_BYTES (8 * 64 * QP * 2 + 64 * 68 * 4 + 3 * 64 * 4)

__global__ __launch_bounds__(256) void attn_mma_kernel(
    const float* __restrict__ qkv, float* __restrict__ z)
{
    extern __shared__ char smraw[];
    __nv_bfloat16* Qh = (__nv_bfloat16*)smraw;
    __nv_bfloat16* Ql = Qh + 64 * QP;
    __nv_bfloat16* Kh = Ql + 64 * QP;
    __nv_bfloat16* Kl = Kh + 64 * QP;
    __nv_bfloat16* Vh = Kl + 64 * QP;
    __nv_bfloat16* Vl = Vh + 64 * QP;
    __nv_bfloat16* Ph = Vl + 64 * QP;
    __nv_bfloat16* Pl = Ph + 64 * QP;
    float* Ss   = (float*)(Pl + 64 * QP);   // [64][68]
    float* mrow = Ss + 64 * 68;
    float* lrow = mrow + 64;
    float* alph = lrow + 64;

    const int t    = threadIdx.x;
    const int lane = t & 31;
    const int warp = t >> 5;
    const int g    = lane >> 2;
    const int tig  = lane & 3;
    const int wm   = warp >> 1;            // 0..3 -> rows wm*16
    const int wn   = warp & 1;             // 0..1 -> cols wn*32
    const int qt   = (S_LEN / 64 - 1) - blockIdx.x;  // big tiles first
    const int bh   = blockIdx.y;
    const int b    = bh >> 4;
    const int h    = bh & 15;

    const unsigned qh_b = (unsigned)__cvta_generic_to_shared(Qh);
    const unsigned ql_b = (unsigned)__cvta_generic_to_shared(Ql);
    const unsigned kh_b = (unsigned)__cvta_generic_to_shared(Kh);
    const unsigned kl_b = (unsigned)__cvta_generic_to_shared(Kl);
    const unsigned vh_b = (unsigned)__cvta_generic_to_shared(Vh);
    const unsigned vl_b = (unsigned)__cvta_generic_to_shared(Vl);
    const unsigned ph_b = (unsigned)__cvta_generic_to_shared(Ph);
    const unsigned pl_b = (unsigned)__cvta_generic_to_shared(Pl);

    const size_t rs = QKV_COLS;
    const float* qbase = qkv + (size_t)(b * S_LEN + qt * 64) * rs + h * HD;

    // Load + split Q tile: [64 rows][64 dims]
#pragma unroll
    for (int i = 0; i < 4; i++) {
        int idx = i * 256 + t;
        int r = idx >> 4, gq = idx & 15;
        float4 v = *(const float4*)(qbase + (size_t)r * rs + (gq << 2));
        unsigned h01, h23, l01, l23;
        split4(v, h01, h23, l01, l23);
        *reinterpret_cast<unsigned*>(&Qh[r * QP + gq * 4])     = h01;
        *reinterpret_cast<unsigned*>(&Qh[r * QP + gq * 4 + 2]) = h23;
        *reinterpret_cast<unsigned*>(&Ql[r * QP + gq * 4])     = l01;
        *reinterpret_cast<unsigned*>(&Ql[r * QP + gq * 4 + 2]) = l23;
    }
    if (t < 64) { mrow[t] = -1e30f; lrow[t] = 0.f; }

    float o[4][4];
#pragma unroll
    for (int i = 0; i < 4; i++)
#pragma unroll
        for (int j = 0; j < 4; j++) o[i][j] = 0.f;

    for (int kt = 0; kt <= qt; kt++) {
        // ---- Load + split K and V tiles ----
        const float* kbase = qkv + (size_t)(b * S_LEN + kt * 64) * rs + D_MODEL + h * HD;
        const float* vbase = kbase + D_MODEL;
#pragma unroll
        for (int i = 0; i < 4; i++) {
            int idx = i * 256 + t;
            int r = idx >> 4, gq = idx & 15;
            {
                float4 v = *(const float4*)(kbase + (size_t)r * rs + (gq << 2));
                unsigned h01, h23, l01, l23;
                split4(v, h01, h23, l01, l23);
                *reinterpret_cast<unsigned*>(&Kh[r * QP + gq * 4])     = h01;
                *reinterpret_cast<unsigned*>(&Kh[r * QP + gq * 4 + 2]) = h23;
                *reinterpret_cast<unsigned*>(&Kl[r * QP + gq * 4])     = l01;
                *reinterpret_cast<unsigned*>(&Kl[r * QP + gq * 4 + 2]) = l23;
            }
            {
                float4 v = *(const float4*)(vbase + (size_t)r * rs + (gq << 2));
                unsigned h01, h23, l01, l23;
                split4(v, h01, h23, l01, l23);
                *reinterpret_cast<unsigned*>(&Vh[r * QP + gq * 4])     = h01;
                *reinterpret_cast<unsigned*>(&Vh[r * QP + gq * 4 + 2]) = h23;
                *reinterpret_cast<unsigned*>(&Vl[r * QP + gq * 4])     = l01;
                *reinterpret_cast<unsigned*>(&Vl[r * QP + gq * 4 + 2]) = l23;
            }
        }
        __syncthreads();

        // ---- S = Q K^T (split bf16 mma) ----
        float sa[4][4];
#pragma unroll
        for (int i = 0; i < 4; i++)
#pragma unroll
            for (int j = 0; j < 4; j++) sa[i][j] = 0.f;

#pragma unroll
        for (int kc = 0; kc < 64; kc += 16) {
            unsigned aH[4], aL[4];
            const unsigned aoff =
                (unsigned)(((wm << 4) + (lane & 15)) * (QP * 2) + (kc + ((lane >> 4) << 3)) * 2);
            ldsm_x4(aH, qh_b + aoff);
            ldsm_x4(aL, ql_b + aoff);
#pragma unroll
            for (int nt = 0; nt < 4; nt++) {
                const int nb = (wn << 5) + (nt << 3);
                const unsigned boff =
                    (unsigned)((nb + (lane & 7)) * (QP * 2) + (kc + (((lane >> 3) & 1) << 3)) * 2);
                unsigned bH[2], bL[2];
                ldsm_x2(bH, kh_b + boff);
                ldsm_x2(bL, kl_b + boff);
                mma_bf16(sa[nt], aH[0], aH[1], aH[2], aH[3], bH[0], bH[1]);
                mma_bf16(sa[nt], aL[0], aL[1], aL[2], aL[3], bH[0], bH[1]);
                mma_bf16(sa[nt], aH[0], aH[1], aH[2], aH[3], bL[0], bL[1]);
            }
        }

        // scale + causal mask + stage fp32 to smem
        {
            const bool diag = (kt == qt);
            const int r0l = (wm << 4) + g;
            const int r1l = r0l + 8;
#pragma unroll
            for (int nt = 0; nt < 4; nt++) {
                const int cb = (wn << 5) + (nt << 3) + (tig << 1);
                float v0 = sa[nt][0] * 0.125f;
                float v1 = sa[nt][1] * 0.125f;
                float v2 = sa[nt][2] * 0.125f;
                float v3 = sa[nt][3] * 0.125f;
                if (diag) {
                    if (cb     > r0l) v0 = -1e30f;
                    if (cb + 1 > r0l) v1 = -1e30f;
                    if (cb     > r1l) v2 = -1e30f;
                    if (cb + 1 > r1l) v3 = -1e30f;
                }
                float2 w0 = {v0, v1}, w1 = {v2, v3};
                *(float2*)&Ss[r0l * 68 + cb] = w0;
                *(float2*)&Ss[r1l * 68 + cb] = w1;
            }
        }
        __syncthreads();

        // ---- online softmax (fp32), emit P as split bf16 ----
        {
            const int r  = t >> 2;
            const int qq = t & 3;
            float* srow = &Ss[r * 68 + qq * 16];
            float4 v0 = *(float4*)&srow[0];
            float4 v1 = *(float4*)&srow[4];
            float4 v2 = *(float4*)&srow[8];
            float4 v3 = *(float4*)&srow[12];
            float mloc = fmaxf(fmaxf(fmaxf(v0.x, v0.y), fmaxf(v0.z, v0.w)),
                               fmaxf(fmaxf(v1.x, v1.y), fmaxf(v1.z, v1.w)));
            mloc = fmaxf(mloc, fmaxf(fmaxf(v2.x, v2.y), fmaxf(v2.z, v2.w)));
            mloc = fmaxf(mloc, fmaxf(fmaxf(v3.x, v3.y), fmaxf(v3.z, v3.w)));
            mloc = fmaxf(mloc, __shfl_xor_sync(0xffffffffu, mloc, 1));
            mloc = fmaxf(mloc, __shfl_xor_sync(0xffffffffu, mloc, 2));
            float mold = mrow[r];
            float mnew = fmaxf(mold, mloc);

            float p[16];
            p[0]  = __expf(v0.x - mnew); p[1]  = __expf(v0.y - mnew);
            p[2]  = __expf(v0.z - mnew); p[3]  = __expf(v0.w - mnew);
            p[4]  = __expf(v1.x - mnew); p[5]  = __expf(v1.y - mnew);
            p[6]  = __expf(v1.z - mnew); p[7]  = __expf(v1.w - mnew);
            p[8]  = __expf(v2.x - mnew); p[9]  = __expf(v2.y - mnew);
            p[10] = __expf(v2.z - mnew); p[11] = __expf(v2.w - mnew);
            p[12] = __expf(v3.x - mnew); p[13] = __expf(v3.y - mnew);
            p[14] = __expf(v3.z - mnew); p[15] = __expf(v3.w - mnew);

            float lsum = 0.f;
#pragma unroll
            for (int e = 0; e < 16; e++) lsum += p[e];

            const int cbase = r * QP + qq * 16;
#pragma unroll
            for (int e = 0; e < 16; e += 4) {
                float4 pv = {p[e], p[e + 1], p[e + 2], p[e + 3]};
                unsigned h01, h23, l01, l23;
                split4(pv, h01, h23, l01, l23);
                *reinterpret_cast<unsigned*>(&Ph[cbase + e])     = h01;
                *reinterpret_cast<unsigned*>(&Ph[cbase + e + 2]) = h23;
                *reinterpret_cast<unsigned*>(&Pl[cbase + e])     = l01;
                *reinterpret_cast<unsigned*>(&Pl[cbase + e + 2]) = l23;
            }

            lsum += __shfl_xor_sync(0xffffffffu, lsum, 1);
            lsum += __shfl_xor_sync(0xffffffffu, lsum, 2);
            if (qq == 0) {
                float alpha = __expf(mold - mnew);
                lrow[r] = lrow[r] * alpha + lsum;
                mrow[r] = mnew;
                alph[r] = alpha;
            }
        }
        __syncthreads();

        // ---- O = O*alpha + P V (split bf16 mma) ----
        {
            const float a0 = alph[(wm << 4) + g];
            const float a1 = alph[(wm << 4) + g + 8];
#pragma unroll
            for (int nt = 0; nt < 4; nt++) {
                o[nt][0] *= a0; o[nt][1] *= a0;
                o[nt][2] *= a1; o[nt][3] *= a1;
            }
#pragma unroll
            for (int kc = 0; kc < 64; kc += 16) {
                unsigned pH[4], pL[4];
                const unsigned poff =
                    (unsigned)(((wm << 4) + (lane & 15)) * (QP * 2) + (kc + ((lane >> 4) << 3)) * 2);
                ldsm_x4(pH, ph_b + poff);
                ldsm_x4(pL, pl_b + poff);
#pragma unroll
                for (int nt = 0; nt < 4; nt++) {
                    const int nb = (wn << 5) + (nt << 3);
                    const unsigned voff =
                        (unsigned)((kc + (lane & 15)) * (QP * 2) + nb * 2);
                    unsigned vH[2], vL[2];
                    ldsm_x2t(vH, vh_b + voff);
                    ldsm_x2t(vL, vl_b + voff);
                    mma_bf16(o[nt], pH[0], pH[1], pH[2], pH[3], vH[0], vH[1]);
                    mma_bf16(o[nt], pL[0], pL[1], pL[2], pL[3], vH[0], vH[1]);
                    mma_bf16(o[nt], pH[0], pH[1], pH[2], pH[3], vL[0], vL[1]);
                }
            }
        }
        __syncthreads();
    }

    // Epilogue: divide by l, write z[b, s, h*64 + col]
    {
        const float l0 = 1.f / lrow[(wm << 4) + g];
        const float l1 = 1.f / lrow[(wm << 4) + g + 8];
        const int row0 = qt * 64 + (wm << 4) + g;
        const int row1 = row0 + 8;
#pragma unroll
        for (int nt = 0; nt < 4; nt++) {
            const int col = (wn << 5) + (nt << 3) + (tig << 1);
            float2 w0 = {o[nt][0] * l0, o[nt][1] * l0};
            float2 w1 = {o[nt][2] * l1, o[nt][3] * l1};
            *(float2*)(z + (size_t)(b * S_LEN + row0) * D_MODEL + h * HD + col) = w0;
            *(float2*)(z + (size_t)(b * S_LEN + row1) * D_MODEL + h * HD + col) = w1;
        }
    }
}

// ---------------------------------------------------------------------------
extern "C" void kernel_launch(void* const* d_in, const int* in_sizes, int n_in,
                              void* d_out, int out_size)
{
    const float* x     = (const float*)d_in[0];
    const float* w_qkv = (const float*)d_in[1];
    const float* b_qkv = (const float*)d_in[2];
    const float* w_out = (const float*)d_in[3];
    const float* b_out = (const float*)d_in[4];
    float* out = (float*)d_out;

    float* qkv_ptr = nullptr;
    float* z_ptr   = nullptr;
    cudaGetSymbolAddress((void**)&qkv_ptr, g_qkv);
    cudaGetSymbolAddress((void**)&z_ptr, g_z);

    cudaFuncSetAttribute(attn_mma_kernel,
                         cudaFuncAttributeMaxDynamicSharedMemorySize,
                         ATT2_SMEM_BYTES);

    // 1) QKV GEMM: [4096,1024] @ [1024,3072] + bias
    {
        dim3 grid(QKV_COLS / 128, M_ROWS / 128);
        gemm_bf16s_kernel<<<grid, 256>>>(x, w_qkv, b_qkv, qkv_ptr,
                                         M_ROWS, QKV_COLS, D_MODEL);
    }
    // 2) Causal flash attention (tensor-core)
    {
        dim3 grid(S_LEN / 64, B_SZ * NH);
        attn_mma_kernel<<<grid, 256, ATT2_SMEM_BYTES>>>(qkv_ptr, z_ptr);
    }
    // 3) Output GEMM: [4096,1024] @ [1024,1024] + bias
    {
        dim3 grid(D_MODEL / 128, M_ROWS / 128);
        gemm_bf16s_kernel<<<grid, 256>>>(z_ptr, w_out, b_out, out,
                                         M_ROWS, D_MODEL, D_MODEL);
    }
}

// round 6
// speedup vs baseline: 2.4633x; 1.0819x over previous
#include <cuda_runtime.h>
#include <cuda_bf16.h>
#include <math.h>

#define S_LEN 2048
#define B_SZ 2
#define D_MODEL 1024
#define NH 16
#define HD 64
#define M_ROWS (B_SZ * S_LEN)   // 4096
#define QKV_COLS (3 * D_MODEL)  // 3072

// Pre-split bf16 hi/lo buffers
__device__ __nv_bfloat16 g_xh[(size_t)M_ROWS * D_MODEL];
__device__ __nv_bfloat16 g_xl[(size_t)M_ROWS * D_MODEL];
__device__ __nv_bfloat16 g_wqh[(size_t)D_MODEL * QKV_COLS];
__device__ __nv_bfloat16 g_wql[(size_t)D_MODEL * QKV_COLS];
__device__ __nv_bfloat16 g_woh[(size_t)D_MODEL * D_MODEL];
__device__ __nv_bfloat16 g_wol[(size_t)D_MODEL * D_MODEL];
__device__ __nv_bfloat16 g_qkvh[(size_t)M_ROWS * QKV_COLS];
__device__ __nv_bfloat16 g_qkvl[(size_t)M_ROWS * QKV_COLS];
__device__ __nv_bfloat16 g_zh[(size_t)M_ROWS * D_MODEL];
__device__ __nv_bfloat16 g_zl[(size_t)M_ROWS * D_MODEL];

// ---------------------------------------------------------------------------
// helpers
// ---------------------------------------------------------------------------
__device__ __forceinline__ unsigned pack_bf2(float x, float y) {
    __nv_bfloat162 h = __floats2bfloat162_rn(x, y);
    return *reinterpret_cast<unsigned*>(&h);
}

__device__ __forceinline__ void mma_bf16(float* c,
                                         unsigned a0, unsigned a1,
                                         unsigned a2, unsigned a3,
                                         unsigned b0, unsigned b1) {
    asm volatile(
        "mma.sync.aligned.m16n8k16.row.col.f32.bf16.bf16.f32 "
        "{%0,%1,%2,%3}, {%4,%5,%6,%7}, {%8,%9}, {%0,%1,%2,%3};\n"
        : "+f"(c[0]), "+f"(c[1]), "+f"(c[2]), "+f"(c[3])
        : "r"(a0), "r"(a1), "r"(a2), "r"(a3), "r"(b0), "r"(b1));
}

__device__ __forceinline__ void ldsm_x4(unsigned r[4], unsigned addr) {
    asm volatile("ldmatrix.sync.aligned.m8n8.x4.shared.b16 {%0,%1,%2,%3}, [%4];"
                 : "=r"(r[0]), "=r"(r[1]), "=r"(r[2]), "=r"(r[3]) : "r"(addr));
}
__device__ __forceinline__ void ldsm_x2(unsigned r[2], unsigned addr) {
    asm volatile("ldmatrix.sync.aligned.m8n8.x2.shared.b16 {%0,%1}, [%2];"
                 : "=r"(r[0]), "=r"(r[1]) : "r"(addr));
}
__device__ __forceinline__ void ldsm_x2t(unsigned r[2], unsigned addr) {
    asm volatile("ldmatrix.sync.aligned.m8n8.x2.trans.shared.b16 {%0,%1}, [%2];"
                 : "=r"(r[0]), "=r"(r[1]) : "r"(addr));
}

__device__ __forceinline__ void split4(float4 v,
                                       unsigned& h01, unsigned& h23,
                                       unsigned& l01, unsigned& l23) {
    float f[4] = {v.x, v.y, v.z, v.w};
    float hi[4], lo[4];
#pragma unroll
    for (int e = 0; e < 4; e++) {
        __nv_bfloat16 h = __float2bfloat16_rn(f[e]);
        hi[e] = __bfloat162float(h);
        lo[e] = f[e] - hi[e];
    }
    h01 = pack_bf2(hi[0], hi[1]); h23 = pack_bf2(hi[2], hi[3]);
    l01 = pack_bf2(lo[0], lo[1]); l23 = pack_bf2(lo[2], lo[3]);
}

__device__ __forceinline__ void cp16(unsigned dst, const void* src) {
    asm volatile("cp.async.cg.shared.global [%0], [%1], 16;\n" :: "r"(dst), "l"(src));
}
#define CP_COMMIT() asm volatile("cp.async.commit_group;\n")
#define CP_WAIT1()  asm volatile("cp.async.wait_group 1;\n")

// ---------------------------------------------------------------------------
// fp32 -> bf16 hi/lo split (elementwise)
// ---------------------------------------------------------------------------
__global__ void split_kernel(const float* __restrict__ src,
                             __nv_bfloat16* __restrict__ h,
                             __nv_bfloat16* __restrict__ l, int n4)
{
    int i = blockIdx.x * blockDim.x + threadIdx.x;
    if (i < n4) {
        float4 v = reinterpret_cast<const float4*>(src)[i];
        unsigned h01, h23, l01, l23;
        split4(v, h01, h23, l01, l23);
        reinterpret_cast<unsigned*>(h)[i * 2]     = h01;
        reinterpret_cast<unsigned*>(h)[i * 2 + 1] = h23;
        reinterpret_cast<unsigned*>(l)[i * 2]     = l01;
        reinterpret_cast<unsigned*>(l)[i * 2 + 1] = l23;
    }
}

// ---------------------------------------------------------------------------
// bf16 (pre-split) tensor-core GEMM, cp.async double-buffered.
// C = Ah@Wh + Al@Wh + Ah@Wl + bias. BM=BN=128, BK=32, 8 warps (2x4),
// warp tile 64x32, m16n8k16. Output: fp32 (splitOut=0) or split bf16 pair.
// ---------------------------------------------------------------------------
#define AP 40    // A smem pitch (bf16)
#define WP 136   // W smem pitch (bf16)
#define AS (128 * AP)
#define WS (32 * WP)
#define STG (2 * AS + 2 * WS)                 // elems per stage
#define GEMM_SMEM_BYTES (2 * STG * 2)         // 2 stages, bf16

__global__ __launch_bounds__(256, 2) void gemm_bf16pre_kernel(
    const __nv_bfloat16* __restrict__ Ahg, const __nv_bfloat16* __restrict__ Alg,
    const __nv_bfloat16* __restrict__ Whg, const __nv_bfloat16* __restrict__ Wlg,
    const float* __restrict__ bias,
    float* __restrict__ Cf,
    __nv_bfloat16* __restrict__ Ch, __nv_bfloat16* __restrict__ Cl,
    int M, int N, int K, int splitOut)
{
    extern __shared__ __nv_bfloat16 smg[];
    const unsigned sbase = (unsigned)__cvta_generic_to_shared(smg);

    const int t    = threadIdx.x;
    const int lane = t & 31;
    const int warp = t >> 5;
    const int g    = lane >> 2;
    const int tig  = lane & 3;
    const int wm   = warp >> 2;
    const int wn   = warp & 3;
    const int m0   = blockIdx.y << 7;
    const int n0   = blockIdx.x << 7;

    float acc[4][4][4];
#pragma unroll
    for (int i = 0; i < 4; i++)
#pragma unroll
        for (int j = 0; j < 4; j++)
#pragma unroll
            for (int r = 0; r < 4; r++) acc[i][j][r] = 0.f;

    auto issue = [&](int it, int stg) {
        const int k0 = it << 5;
        const unsigned base = sbase + (unsigned)(stg * STG * 2);
#pragma unroll
        for (int c = t; c < 512; c += 256) {
            const int row = c >> 2, off = (c & 3) << 3;
            const size_t s = (size_t)(m0 + row) * K + k0 + off;
            cp16(base + (unsigned)((row * AP + off) * 2), Ahg + s);
            cp16(base + (unsigned)((AS + row * AP + off) * 2), Alg + s);
        }
#pragma unroll
        for (int c = t; c < 512; c += 256) {
            const int row = c >> 4, off = (c & 15) << 3;
            const size_t s = (size_t)(k0 + row) * N + n0 + off;
            cp16(base + (unsigned)((2 * AS + row * WP + off) * 2), Whg + s);
            cp16(base + (unsigned)((2 * AS + WS + row * WP + off) * 2), Wlg + s);
        }
    };

    issue(0, 0);
    CP_COMMIT();

    const int NIT = K >> 5;
    for (int it = 0; it < NIT; it++) {
        if (it + 1 < NIT) issue(it + 1, (it + 1) & 1);
        CP_COMMIT();
        CP_WAIT1();
        __syncthreads();

        const unsigned ah_b = sbase + (unsigned)((it & 1) * STG * 2);
        const unsigned al_b = ah_b + AS * 2;
        const unsigned wh_b = ah_b + 2 * AS * 2;
        const unsigned wl_b = wh_b + WS * 2;

#pragma unroll
        for (int kc = 0; kc < 32; kc += 16) {
            unsigned ahi[4][4], alo[4][4];
#pragma unroll
            for (int mt = 0; mt < 4; mt++) {
                const int row = (wm << 6) + (mt << 4) + (lane & 15);
                const int col = kc + ((lane >> 4) << 3);
                const unsigned off = (unsigned)(row * (AP * 2) + col * 2);
                ldsm_x4(ahi[mt], ah_b + off);
                ldsm_x4(alo[mt], al_b + off);
            }
#pragma unroll
            for (int nt = 0; nt < 4; nt++) {
                const int krow = kc + (lane & 15);
                const int ncol = (wn << 5) + (nt << 3);
                const unsigned off = (unsigned)(krow * (WP * 2) + ncol * 2);
                unsigned bh[2], bl[2];
                ldsm_x2t(bh, wh_b + off);
                ldsm_x2t(bl, wl_b + off);
#pragma unroll
                for (int mt = 0; mt < 4; mt++) {
                    mma_bf16(acc[mt][nt], ahi[mt][0], ahi[mt][1], ahi[mt][2], ahi[mt][3], bh[0], bh[1]);
                    mma_bf16(acc[mt][nt], alo[mt][0], alo[mt][1], alo[mt][2], alo[mt][3], bh[0], bh[1]);
                    mma_bf16(acc[mt][nt], ahi[mt][0], ahi[mt][1], ahi[mt][2], ahi[mt][3], bl[0], bl[1]);
                }
            }
        }
        __syncthreads();
    }

    // Epilogue
#pragma unroll
    for (int mt = 0; mt < 4; mt++) {
        const int row0 = m0 + (wm << 6) + (mt << 4) + g;
        const int row1 = row0 + 8;
#pragma unroll
        for (int nt = 0; nt < 4; nt++) {
            const int col = n0 + (wn << 5) + (nt << 3) + (tig << 1);
            const float b0 = bias[col];
            const float b1 = bias[col + 1];
            float v00 = acc[mt][nt][0] + b0, v01 = acc[mt][nt][1] + b1;
            float v10 = acc[mt][nt][2] + b0, v11 = acc[mt][nt][3] + b1;
            if (!splitOut) {
                float2 w0 = {v00, v01}, w1 = {v10, v11};
                *(float2*)(Cf + (size_t)row0 * N + col) = w0;
                *(float2*)(Cf + (size_t)row1 * N + col) = w1;
            } else {
                __nv_bfloat16 h00 = __float2bfloat16_rn(v00);
                __nv_bfloat16 h01 = __float2bfloat16_rn(v01);
                __nv_bfloat16 h10 = __float2bfloat16_rn(v10);
                __nv_bfloat16 h11 = __float2bfloat16_rn(v11);
                float l00 = v00 - __bfloat162float(h00);
                float l01 = v01 - __bfloat162float(h01);
                float l10 = v10 - __bfloat162float(h10);
                float l11 = v11 - __bfloat162float(h11);
                unsigned hp0, hp1;
                __nv_bfloat162 t0 = {h00, h01}; hp0 = *reinterpret_cast<unsigned*>(&t0);
                __nv_bfloat162 t1 = {h10, h11}; hp1 = *reinterpret_cast<unsigned*>(&t1);
                *reinterpret_cast<unsigned*>(Ch + (size_t)row0 * N + col) = hp0;
                *reinterpret_cast<unsigned*>(Ch + (size_t)row1 * N + col) = hp1;
                *reinterpret_cast<unsigned*>(Cl + (size_t)row0 * N + col) = pack_bf2(l00, l01);
                *reinterpret_cast<unsigned*>(Cl + (size_t)row1 * N + col) = pack_bf2(l10, l11);
            }
        }
    }
}

// ---------------------------------------------------------------------------
// Flash attention (causal), bf16-split MMA, pre-split qkv inputs.
// Structure identical to round 5 (verified); loads are now plain bf16 copies
// and z is emitted as split bf16 (zh, zl).
// ---------------------------------------------------------------------------
#define QP 72
#define ATT2_SMEM_BYTES (8 * 64 * QP * 2 + 64 * 68 * 4 + 3 * 64 * 4)

__global__ __launch_bounds__(256) void attn_mma_kernel(
    const __nv_bfloat16* __restrict__ qkvh, const __nv_bfloat16* __restrict__ qkvl,
    __nv_bfloat16* __restrict__ zh, __nv_bfloat16* __restrict__ zl)
{
    extern __shared__ char smraw[];
    __nv_bfloat16* Qh = (__nv_bfloat16*)smraw;
    __nv_bfloat16* Ql = Qh + 64 * QP;
    __nv_bfloat16* Kh = Ql + 64 * QP;
    __nv_bfloat16* Kl = Kh + 64 * QP;
    __nv_bfloat16* Vh = Kl + 64 * QP;
    __nv_bfloat16* Vl = Vh + 64 * QP;
    __nv_bfloat16* Ph = Vl + 64 * QP;
    __nv_bfloat16* Pl = Ph + 64 * QP;
    float* Ss   = (float*)(Pl + 64 * QP);
    float* mrow = Ss + 64 * 68;
    float* lrow = mrow + 64;
    float* alph = lrow + 64;

    const int t    = threadIdx.x;
    const int lane = t & 31;
    const int warp = t >> 5;
    const int g    = lane >> 2;
    const int tig  = lane & 3;
    const int wm   = warp >> 1;
    const int wn   = warp & 1;
    const int qt   = (S_LEN / 64 - 1) - blockIdx.x;
    const int bh   = blockIdx.y;
    const int b    = bh >> 4;
    const int h    = bh & 15;

    const unsigned qh_b = (unsigned)__cvta_generic_to_shared(Qh);
    const unsigned ql_b = (unsigned)__cvta_generic_to_shared(Ql);
    const unsigned kh_b = (unsigned)__cvta_generic_to_shared(Kh);
    const unsigned kl_b = (unsigned)__cvta_generic_to_shared(Kl);
    const unsigned vh_b = (unsigned)__cvta_generic_to_shared(Vh);
    const unsigned vl_b = (unsigned)__cvta_generic_to_shared(Vl);
    const unsigned ph_b = (unsigned)__cvta_generic_to_shared(Ph);
    const unsigned pl_b = (unsigned)__cvta_generic_to_shared(Pl);

    const size_t rs = QKV_COLS;
    const size_t qoff = (size_t)(b * S_LEN + qt * 64) * rs + h * HD;

    // Load Q tile (bf16 hi/lo, 8-elem chunks)
#pragma unroll
    for (int i = 0; i < 2; i++) {
        int idx = i * 256 + t;
        int r = idx >> 3, c8 = (idx & 7) << 3;
        float4 vh4 = *(const float4*)(qkvh + qoff + (size_t)r * rs + c8);
        float4 vl4 = *(const float4*)(qkvl + qoff + (size_t)r * rs + c8);
        *(float4*)&Qh[r * QP + c8] = vh4;
        *(float4*)&Ql[r * QP + c8] = vl4;
    }
    if (t < 64) { mrow[t] = -1e30f; lrow[t] = 0.f; }

    float o[4][4];
#pragma unroll
    for (int i = 0; i < 4; i++)
#pragma unroll
        for (int j = 0; j < 4; j++) o[i][j] = 0.f;

    for (int kt = 0; kt <= qt; kt++) {
        const size_t koff = (size_t)(b * S_LEN + kt * 64) * rs + D_MODEL + h * HD;
        const size_t voff = koff + D_MODEL;
#pragma unroll
        for (int i = 0; i < 2; i++) {
            int idx = i * 256 + t;
            int r = idx >> 3, c8 = (idx & 7) << 3;
            float4 a = *(const float4*)(qkvh + koff + (size_t)r * rs + c8);
            float4 c = *(const float4*)(qkvl + koff + (size_t)r * rs + c8);
            float4 d = *(const float4*)(qkvh + voff + (size_t)r * rs + c8);
            float4 e = *(const float4*)(qkvl + voff + (size_t)r * rs + c8);
            *(float4*)&Kh[r * QP + c8] = a;
            *(float4*)&Kl[r * QP + c8] = c;
            *(float4*)&Vh[r * QP + c8] = d;
            *(float4*)&Vl[r * QP + c8] = e;
        }
        __syncthreads();

        // S = Q K^T
        float sa[4][4];
#pragma unroll
        for (int i = 0; i < 4; i++)
#pragma unroll
            for (int j = 0; j < 4; j++) sa[i][j] = 0.f;

#pragma unroll
        for (int kc = 0; kc < 64; kc += 16) {
            unsigned aH[4], aL[4];
            const unsigned aoff =
                (unsigned)(((wm << 4) + (lane & 15)) * (QP * 2) + (kc + ((lane >> 4) << 3)) * 2);
            ldsm_x4(aH, qh_b + aoff);
            ldsm_x4(aL, ql_b + aoff);
#pragma unroll
            for (int nt = 0; nt < 4; nt++) {
                const int nb = (wn << 5) + (nt << 3);
                const unsigned boff =
                    (unsigned)((nb + (lane & 7)) * (QP * 2) + (kc + (((lane >> 3) & 1) << 3)) * 2);
                unsigned bH[2], bL[2];
                ldsm_x2(bH, kh_b + boff);
                ldsm_x2(bL, kl_b + boff);
                mma_bf16(sa[nt], aH[0], aH[1], aH[2], aH[3], bH[0], bH[1]);
                mma_bf16(sa[nt], aL[0], aL[1], aL[2], aL[3], bH[0], bH[1]);
                mma_bf16(sa[nt], aH[0], aH[1], aH[2], aH[3], bL[0], bL[1]);
            }
        }

        {
            const bool diag = (kt == qt);
            const int r0l = (wm << 4) + g;
            const int r1l = r0l + 8;
#pragma unroll
            for (int nt = 0; nt < 4; nt++) {
                const int cb = (wn << 5) + (nt << 3) + (tig << 1);
                float v0 = sa[nt][0] * 0.125f;
                float v1 = sa[nt][1] * 0.125f;
                float v2 = sa[nt][2] * 0.125f;
                float v3 = sa[nt][3] * 0.125f;
                if (diag) {
                    if (cb     > r0l) v0 = -1e30f;
                    if (cb + 1 > r0l) v1 = -1e30f;
                    if (cb     > r1l) v2 = -1e30f;
                    if (cb + 1 > r1l) v3 = -1e30f;
                }
                float2 w0 = {v0, v1}, w1 = {v2, v3};
                *(float2*)&Ss[r0l * 68 + cb] = w0;
                *(float2*)&Ss[r1l * 68 + cb] = w1;
            }
        }
        __syncthreads();

        // online softmax, emit split P
        {
            const int r  = t >> 2;
            const int qq = t & 3;
            float* srow = &Ss[r * 68 + qq * 16];
            float4 v0 = *(float4*)&srow[0];
            float4 v1 = *(float4*)&srow[4];
            float4 v2 = *(float4*)&srow[8];
            float4 v3 = *(float4*)&srow[12];
            float mloc = fmaxf(fmaxf(fmaxf(v0.x, v0.y), fmaxf(v0.z, v0.w)),
                               fmaxf(fmaxf(v1.x, v1.y), fmaxf(v1.z, v1.w)));
            mloc = fmaxf(mloc, fmaxf(fmaxf(v2.x, v2.y), fmaxf(v2.z, v2.w)));
            mloc = fmaxf(mloc, fmaxf(fmaxf(v3.x, v3.y), fmaxf(v3.z, v3.w)));
            mloc = fmaxf(mloc, __shfl_xor_sync(0xffffffffu, mloc, 1));
            mloc = fmaxf(mloc, __shfl_xor_sync(0xffffffffu, mloc, 2));
            float mold = mrow[r];
            float mnew = fmaxf(mold, mloc);

            float p[16];
            p[0]  = __expf(v0.x - mnew); p[1]  = __expf(v0.y - mnew);
            p[2]  = __expf(v0.z - mnew); p[3]  = __expf(v0.w - mnew);
            p[4]  = __expf(v1.x - mnew); p[5]  = __expf(v1.y - mnew);
            p[6]  = __expf(v1.z - mnew); p[7]  = __expf(v1.w - mnew);
            p[8]  = __expf(v2.x - mnew); p[9]  = __expf(v2.y - mnew);
            p[10] = __expf(v2.z - mnew); p[11] = __expf(v2.w - mnew);
            p[12] = __expf(v3.x - mnew); p[13] = __expf(v3.y - mnew);
            p[14] = __expf(v3.z - mnew); p[15] = __expf(v3.w - mnew);

            float lsum = 0.f;
#pragma unroll
            for (int e = 0; e < 16; e++) lsum += p[e];

            const int cbase = r * QP + qq * 16;
#pragma unroll
            for (int e = 0; e < 16; e += 4) {
                float4 pv = {p[e], p[e + 1], p[e + 2], p[e + 3]};
                unsigned h01, h23, l01, l23;
                split4(pv, h01, h23, l01, l23);
                *reinterpret_cast<unsigned*>(&Ph[cbase + e])     = h01;
                *reinterpret_cast<unsigned*>(&Ph[cbase + e + 2]) = h23;
                *reinterpret_cast<unsigned*>(&Pl[cbase + e])     = l01;
                *reinterpret_cast<unsigned*>(&Pl[cbase + e + 2]) = l23;
            }

            lsum += __shfl_xor_sync(0xffffffffu, lsum, 1);
            lsum += __shfl_xor_sync(0xffffffffu, lsum, 2);
            if (qq == 0) {
                float alpha = __expf(mold - mnew);
                lrow[r] = lrow[r] * alpha + lsum;
                mrow[r] = mnew;
                alph[r] = alpha;
            }
        }
        __syncthreads();

        // O = O*alpha + P V
        {
            const float a0 = alph[(wm << 4) + g];
            const float a1 = alph[(wm << 4) + g + 8];
#pragma unroll
            for (int nt = 0; nt < 4; nt++) {
                o[nt][0] *= a0; o[nt][1] *= a0;
                o[nt][2] *= a1; o[nt][3] *= a1;
            }
#pragma unroll
            for (int kc = 0; kc < 64; kc += 16) {
                unsigned pH[4], pL[4];
                const unsigned poff =
                    (unsigned)(((wm << 4) + (lane & 15)) * (QP * 2) + (kc + ((lane >> 4) << 3)) * 2);
                ldsm_x4(pH, ph_b + poff);
                ldsm_x4(pL, pl_b + poff);
#pragma unroll
                for (int nt = 0; nt < 4; nt++) {
                    const int nb = (wn << 5) + (nt << 3);
                    const unsigned voff2 =
                        (unsigned)((kc + (lane & 15)) * (QP * 2) + nb * 2);
                    unsigned vH[2], vL[2];
                    ldsm_x2t(vH, vh_b + voff2);
                    ldsm_x2t(vL, vl_b + voff2);
                    mma_bf16(o[nt], pH[0], pH[1], pH[2], pH[3], vH[0], vH[1]);
                    mma_bf16(o[nt], pL[0], pL[1], pL[2], pL[3], vH[0], vH[1]);
                    mma_bf16(o[nt], pH[0], pH[1], pH[2], pH[3], vL[0], vL[1]);
                }
            }
        }
        __syncthreads();
    }

    // Epilogue: divide by l, write split z
    {
        const float l0 = 1.f / lrow[(wm << 4) + g];
        const float l1 = 1.f / lrow[(wm << 4) + g + 8];
        const int row0 = qt * 64 + (wm << 4) + g;
        const int row1 = row0 + 8;
#pragma unroll
        for (int nt = 0; nt < 4; nt++) {
            const int col = (wn << 5) + (nt << 3) + (tig << 1);
            float w00 = o[nt][0] * l0, w01 = o[nt][1] * l0;
            float w10 = o[nt][2] * l1, w11 = o[nt][3] * l1;
            __nv_bfloat16 h00 = __float2bfloat16_rn(w00);
            __nv_bfloat16 h01 = __float2bfloat16_rn(w01);
            __nv_bfloat16 h10 = __float2bfloat16_rn(w10);
            __nv_bfloat16 h11 = __float2bfloat16_rn(w11);
            float l00 = w00 - __bfloat162float(h00);
            float l01v = w01 - __bfloat162float(h01);
            float l10 = w10 - __bfloat162float(h10);
            float l11 = w11 - __bfloat162float(h11);
            size_t o0 = (size_t)(b * S_LEN + row0) * D_MODEL + h * HD + col;
            size_t o1 = (size_t)(b * S_LEN + row1) * D_MODEL + h * HD + col;
            __nv_bfloat162 t0 = {h00, h01};
            __nv_bfloat162 t1 = {h10, h11};
            *reinterpret_cast<unsigned*>(zh + o0) = *reinterpret_cast<unsigned*>(&t0);
            *reinterpret_cast<unsigned*>(zh + o1) = *reinterpret_cast<unsigned*>(&t1);
            *reinterpret_cast<unsigned*>(zl + o0) = pack_bf2(l00, l01v);
            *reinterpret_cast<unsigned*>(zl + o1) = pack_bf2(l10, l11);
        }
    }
}

// ---------------------------------------------------------------------------
extern "C" void kernel_launch(void* const* d_in, const int* in_sizes, int n_in,
                              void* d_out, int out_size)
{
    const float* x     = (const float*)d_in[0];
    const float* w_qkv = (const float*)d_in[1];
    const float* b_qkv = (const float*)d_in[2];
    const float* w_out = (const float*)d_in[3];
    const float* b_out = (const float*)d_in[4];
    float* out = (float*)d_out;

    __nv_bfloat16 *xh, *xl, *wqh, *wql, *woh, *wol, *qkvh, *qkvl, *zh, *zl;
    cudaGetSymbolAddress((void**)&xh, g_xh);
    cudaGetSymbolAddress((void**)&xl, g_xl);
    cudaGetSymbolAddress((void**)&wqh, g_wqh);
    cudaGetSymbolAddress((void**)&wql, g_wql);
    cudaGetSymbolAddress((void**)&woh, g_woh);
    cudaGetSymbolAddress((void**)&wol, g_wol);
    cudaGetSymbolAddress((void**)&qkvh, g_qkvh);
    cudaGetSymbolAddress((void**)&qkvl, g_qkvl);
    cudaGetSymbolAddress((void**)&zh, g_zh);
    cudaGetSymbolAddress((void**)&zl, g_zl);

    cudaFuncSetAttribute(gemm_bf16pre_kernel,
                         cudaFuncAttributeMaxDynamicSharedMemorySize,
                         GEMM_SMEM_BYTES);
    cudaFuncSetAttribute(attn_mma_kernel,
                         cudaFuncAttributeMaxDynamicSharedMemorySize,
                         ATT2_SMEM_BYTES);

    // 0) split inputs/weights to bf16 hi/lo
    {
        int n;
        n = M_ROWS * D_MODEL / 4;
        split_kernel<<<(n + 255) / 256, 256>>>(x, xh, xl, n);
        n = D_MODEL * QKV_COLS / 4;
        split_kernel<<<(n + 255) / 256, 256>>>(w_qkv, wqh, wql, n);
        n = D_MODEL * D_MODEL / 4;
        split_kernel<<<(n + 255) / 256, 256>>>(w_out, woh, wol, n);
    }
    // 1) QKV GEMM -> split bf16 qkv
    {
        dim3 grid(QKV_COLS / 128, M_ROWS / 128);
        gemm_bf16pre_kernel<<<grid, 256, GEMM_SMEM_BYTES>>>(
            xh, xl, wqh, wql, b_qkv, nullptr, qkvh, qkvl,
            M_ROWS, QKV_COLS, D_MODEL, 1);
    }
    // 2) attention -> split bf16 z
    {
        dim3 grid(S_LEN / 64, B_SZ * NH);
        attn_mma_kernel<<<grid, 256, ATT2_SMEM_BYTES>>>(qkvh, qkvl, zh, zl);
    }
    // 3) out GEMM -> fp32 output
    {
        dim3 grid(D_MODEL / 128, M_ROWS / 128);
        gemm_bf16pre_kernel<<<grid, 256, GEMM_SMEM_BYTES>>>(
            zh, zl, woh, wol, b_out, out, nullptr, nullptr,
            M_ROWS, D_MODEL, D_MODEL, 0);
    }
}

// round 10
// speedup vs baseline: 2.4815x; 1.0074x over previous
#include <cuda_runtime.h>
#include <cuda_bf16.h>
#include <math.h>

#define S_LEN 2048
#define B_SZ 2
#define D_MODEL 1024
#define NH 16
#define HD 64
#define M_ROWS 4096
#define QKV_COLS 3072

// Pre-split bf16 hi/lo buffers
__device__ __nv_bfloat16 g_xh[(size_t)M_ROWS * D_MODEL];
__device__ __nv_bfloat16 g_xl[(size_t)M_ROWS * D_MODEL];
__device__ __nv_bfloat16 g_wqh[(size_t)D_MODEL * QKV_COLS];
__device__ __nv_bfloat16 g_wql[(size_t)D_MODEL * QKV_COLS];
__device__ __nv_bfloat16 g_woh[(size_t)D_MODEL * D_MODEL];
__device__ __nv_bfloat16 g_wol[(size_t)D_MODEL * D_MODEL];
__device__ __nv_bfloat16 g_qkvh[(size_t)M_ROWS * QKV_COLS];
__device__ __nv_bfloat16 g_qkvl[(size_t)M_ROWS * QKV_COLS];
__device__ __nv_bfloat16 g_zh[(size_t)M_ROWS * D_MODEL];
__device__ __nv_bfloat16 g_zl[(size_t)M_ROWS * D_MODEL];

// ---------------------------------------------------------------------------
// helpers
// ---------------------------------------------------------------------------
__device__ __forceinline__ unsigned pack_bf2(float x, float y) {
    __nv_bfloat162 h = __floats2bfloat162_rn(x, y);
    return *reinterpret_cast<unsigned*>(&h);
}

__device__ __forceinline__ void mma_bf16(float* c,
                                         unsigned a0, unsigned a1,
                                         unsigned a2, unsigned a3,
                                         unsigned b0, unsigned b1) {
    asm volatile(
        "mma.sync.aligned.m16n8k16.row.col.f32.bf16.bf16.f32 "
        "{%0,%1,%2,%3}, {%4,%5,%6,%7}, {%8,%9}, {%0,%1,%2,%3};\n"
        : "+f"(c[0]), "+f"(c[1]), "+f"(c[2]), "+f"(c[3])
        : "r"(a0), "r"(a1), "r"(a2), "r"(a3), "r"(b0), "r"(b1));
}

__device__ __forceinline__ void ldsm_x4(unsigned r[4], unsigned addr) {
    asm volatile("ldmatrix.sync.aligned.m8n8.x4.shared.b16 {%0,%1,%2,%3}, [%4];"
                 : "=r"(r[0]), "=r"(r[1]), "=r"(r[2]), "=r"(r[3]) : "r"(addr));
}
__device__ __forceinline__ void ldsm_x2(unsigned r[2], unsigned addr) {
    asm volatile("ldmatrix.sync.aligned.m8n8.x2.shared.b16 {%0,%1}, [%2];"
                 : "=r"(r[0]), "=r"(r[1]) : "r"(addr));
}
__device__ __forceinline__ void ldsm_x2t(unsigned r[2], unsigned addr) {
    asm volatile("ldmatrix.sync.aligned.m8n8.x2.trans.shared.b16 {%0,%1}, [%2];"
                 : "=r"(r[0]), "=r"(r[1]) : "r"(addr));
}

__device__ __forceinline__ void split4(float4 v,
                                       unsigned& h01, unsigned& h23,
                                       unsigned& l01, unsigned& l23) {
    float f[4] = {v.x, v.y, v.z, v.w};
    float hi[4], lo[4];
#pragma unroll
    for (int e = 0; e < 4; e++) {
        __nv_bfloat16 h = __float2bfloat16_rn(f[e]);
        hi[e] = __bfloat162float(h);
        lo[e] = f[e] - hi[e];
    }
    h01 = pack_bf2(hi[0], hi[1]); h23 = pack_bf2(hi[2], hi[3]);
    l01 = pack_bf2(lo[0], lo[1]); l23 = pack_bf2(lo[2], lo[3]);
}

__device__ __forceinline__ void cp16(unsigned dst, const void* src) {
    asm volatile("cp.async.cg.shared.global [%0], [%1], 16;\n" :: "r"(dst), "l"(src));
}
#define CP_COMMIT() asm volatile("cp.async.commit_group;\n")
#define CP_WAIT1()  asm volatile("cp.async.wait_group 1;\n")

// ---------------------------------------------------------------------------
// fp32 -> bf16 hi/lo split (elementwise)
// ---------------------------------------------------------------------------
__global__ void split_kernel(const float* __restrict__ src,
                             __nv_bfloat16* __restrict__ h,
                             __nv_bfloat16* __restrict__ l, int n4)
{
    int i = blockIdx.x * blockDim.x + threadIdx.x;
    if (i < n4) {
        float4 v = reinterpret_cast<const float4*>(src)[i];
        unsigned h01, h23, l01, l23;
        split4(v, h01, h23, l01, l23);
        reinterpret_cast<unsigned*>(h)[i * 2]     = h01;
        reinterpret_cast<unsigned*>(h)[i * 2 + 1] = h23;
        reinterpret_cast<unsigned*>(l)[i * 2]     = l01;
        reinterpret_cast<unsigned*>(l)[i * 2 + 1] = l23;
    }
}

// ---------------------------------------------------------------------------
// bf16 (pre-split) tensor-core GEMM, cp.async double-buffered, term-major MMA
// issue order (dependent MMAs on one accumulator are >=16 apart).
// ---------------------------------------------------------------------------
#define AP 40
#define WP 136
#define AS (128 * AP)
#define WS (32 * WP)
#define STG (2 * AS + 2 * WS)
#define GEMM_SMEM_BYTES (2 * STG * 2)

__global__ __launch_bounds__(256, 2) void gemm_bf16pre_kernel(
    const __nv_bfloat16* __restrict__ Ahg, const __nv_bfloat16* __restrict__ Alg,
    const __nv_bfloat16* __restrict__ Whg, const __nv_bfloat16* __restrict__ Wlg,
    const float* __restrict__ bias,
    float* __restrict__ Cf,
    __nv_bfloat16* __restrict__ Ch, __nv_bfloat16* __restrict__ Cl,
    int M, int N, int K, int splitOut)
{
    extern __shared__ __nv_bfloat16 smg[];
    const unsigned sbase = (unsigned)__cvta_generic_to_shared(smg);

    const int t    = threadIdx.x;
    const int lane = t & 31;
    const int warp = t >> 5;
    const int g    = lane >> 2;
    const int tig  = lane & 3;
    const int wm   = warp >> 2;
    const int wn   = warp & 3;
    const int m0   = blockIdx.y << 7;
    const int n0   = blockIdx.x << 7;

    float acc[4][4][4];
#pragma unroll
    for (int i = 0; i < 4; i++)
#pragma unroll
        for (int j = 0; j < 4; j++)
#pragma unroll
            for (int r = 0; r < 4; r++) acc[i][j][r] = 0.f;

    auto issue = [&](int it, int stg) {
        const int k0 = it << 5;
        const unsigned base = sbase + (unsigned)(stg * STG * 2);
#pragma unroll
        for (int c = t; c < 512; c += 256) {
            const int row = c >> 2, off = (c & 3) << 3;
            const size_t s = (size_t)(m0 + row) * K + k0 + off;
            cp16(base + (unsigned)((row * AP + off) * 2), Ahg + s);
            cp16(base + (unsigned)((AS + row * AP + off) * 2), Alg + s);
        }
#pragma unroll
        for (int c = t; c < 512; c += 256) {
            const int row = c >> 4, off = (c & 15) << 3;
            const size_t s = (size_t)(k0 + row) * N + n0 + off;
            cp16(base + (unsigned)((2 * AS + row * WP + off) * 2), Whg + s);
            cp16(base + (unsigned)((2 * AS + WS + row * WP + off) * 2), Wlg + s);
        }
    };

    issue(0, 0);
    CP_COMMIT();

    const int NIT = K >> 5;
    for (int it = 0; it < NIT; it++) {
        if (it + 1 < NIT) issue(it + 1, (it + 1) & 1);
        CP_COMMIT();
        CP_WAIT1();
        __syncthreads();

        const unsigned ah_b = sbase + (unsigned)((it & 1) * STG * 2);
        const unsigned al_b = ah_b + AS * 2;
        const unsigned wh_b = ah_b + 2 * AS * 2;
        const unsigned wl_b = wh_b + WS * 2;

#pragma unroll
        for (int kc = 0; kc < 32; kc += 16) {
            unsigned ahi[4][4], alo[4][4], bh[4][2], bl[4][2];
#pragma unroll
            for (int mt = 0; mt < 4; mt++) {
                const int row = (wm << 6) + (mt << 4) + (lane & 15);
                const int col = kc + ((lane >> 4) << 3);
                const unsigned off = (unsigned)(row * (AP * 2) + col * 2);
                ldsm_x4(ahi[mt], ah_b + off);
                ldsm_x4(alo[mt], al_b + off);
            }
#pragma unroll
            for (int nt = 0; nt < 4; nt++) {
                const int krow = kc + (lane & 15);
                const int ncol = (wn << 5) + (nt << 3);
                const unsigned off = (unsigned)(krow * (WP * 2) + ncol * 2);
                ldsm_x2t(bh[nt], wh_b + off);
                ldsm_x2t(bl[nt], wl_b + off);
            }
            // term-major: 16 independent MMAs per term
#pragma unroll
            for (int mt = 0; mt < 4; mt++)
#pragma unroll
                for (int nt = 0; nt < 4; nt++)
                    mma_bf16(acc[mt][nt], ahi[mt][0], ahi[mt][1], ahi[mt][2], ahi[mt][3],
                             bh[nt][0], bh[nt][1]);
#pragma unroll
            for (int mt = 0; mt < 4; mt++)
#pragma unroll
                for (int nt = 0; nt < 4; nt++)
                    mma_bf16(acc[mt][nt], alo[mt][0], alo[mt][1], alo[mt][2], alo[mt][3],
                             bh[nt][0], bh[nt][1]);
#pragma unroll
            for (int mt = 0; mt < 4; mt++)
#pragma unroll
                for (int nt = 0; nt < 4; nt++)
                    mma_bf16(acc[mt][nt], ahi[mt][0], ahi[mt][1], ahi[mt][2], ahi[mt][3],
                             bl[nt][0], bl[nt][1]);
        }
        __syncthreads();
    }

    // Epilogue
#pragma unroll
    for (int mt = 0; mt < 4; mt++) {
        const int row0 = m0 + (wm << 6) + (mt << 4) + g;
        const int row1 = row0 + 8;
#pragma unroll
        for (int nt = 0; nt < 4; nt++) {
            const int col = n0 + (wn << 5) + (nt << 3) + (tig << 1);
            const float b0 = bias[col];
            const float b1 = bias[col + 1];
            float v00 = acc[mt][nt][0] + b0, v01 = acc[mt][nt][1] + b1;
            float v10 = acc[mt][nt][2] + b0, v11 = acc[mt][nt][3] + b1;
            if (!splitOut) {
                float2 w0 = {v00, v01}, w1 = {v10, v11};
                *(float2*)(Cf + (size_t)row0 * N + col) = w0;
                *(float2*)(Cf + (size_t)row1 * N + col) = w1;
            } else {
                __nv_bfloat16 h00 = __float2bfloat16_rn(v00);
                __nv_bfloat16 h01 = __float2bfloat16_rn(v01);
                __nv_bfloat16 h10 = __float2bfloat16_rn(v10);
                __nv_bfloat16 h11 = __float2bfloat16_rn(v11);
                float l00 = v00 - __bfloat162float(h00);
                float l01 = v01 - __bfloat162float(h01);
                float l10 = v10 - __bfloat162float(h10);
                float l11 = v11 - __bfloat162float(h11);
                __nv_bfloat162 t0 = {h00, h01};
                __nv_bfloat162 t1 = {h10, h11};
                *reinterpret_cast<unsigned*>(Ch + (size_t)row0 * N + col) =
                    *reinterpret_cast<unsigned*>(&t0);
                *reinterpret_cast<unsigned*>(Ch + (size_t)row1 * N + col) =
                    *reinterpret_cast<unsigned*>(&t1);
                *reinterpret_cast<unsigned*>(Cl + (size_t)row0 * N + col) = pack_bf2(l00, l01);
                *reinterpret_cast<unsigned*>(Cl + (size_t)row1 * N + col) = pack_bf2(l10, l11);
            }
        }
    }
}

// ---------------------------------------------------------------------------
// Flash attention (causal), bf16-split MMA, term-major issue order.
// ---------------------------------------------------------------------------
#define QP 72
#define ATT2_SMEM_BYTES (8 * 64 * QP * 2 + 64 * 68 * 4 + 3 * 64 * 4)

__global__ __launch_bounds__(256) void attn_mma_kernel(
    const __nv_bfloat16* __restrict__ qkvh, const __nv_bfloat16* __restrict__ qkvl,
    __nv_bfloat16* __restrict__ zh, __nv_bfloat16* __restrict__ zl)
{
    extern __shared__ char smraw[];
    __nv_bfloat16* Qh = (__nv_bfloat16*)smraw;
    __nv_bfloat16* Ql = Qh + 64 * QP;
    __nv_bfloat16* Kh = Ql + 64 * QP;
    __nv_bfloat16* Kl = Kh + 64 * QP;
    __nv_bfloat16* Vh = Kl + 64 * QP;
    __nv_bfloat16* Vl = Vh + 64 * QP;
    __nv_bfloat16* Ph = Vl + 64 * QP;
    __nv_bfloat16* Pl = Ph + 64 * QP;
    float* Ss   = (float*)(Pl + 64 * QP);
    float* mrow = Ss + 64 * 68;
    float* lrow = mrow + 64;
    float* alph = lrow + 64;

    const int t    = threadIdx.x;
    const int lane = t & 31;
    const int warp = t >> 5;
    const int g    = lane >> 2;
    const int tig  = lane & 3;
    const int wm   = warp >> 1;
    const int wn   = warp & 1;
    const int qt   = (S_LEN / 64 - 1) - blockIdx.x;
    const int bh   = blockIdx.y;
    const int b    = bh >> 4;
    const int h    = bh & 15;

    const unsigned qh_b = (unsigned)__cvta_generic_to_shared(Qh);
    const unsigned ql_b = (unsigned)__cvta_generic_to_shared(Ql);
    const unsigned kh_b = (unsigned)__cvta_generic_to_shared(Kh);
    const unsigned kl_b = (unsigned)__cvta_generic_to_shared(Kl);
    const unsigned vh_b = (unsigned)__cvta_generic_to_shared(Vh);
    const unsigned vl_b = (unsigned)__cvta_generic_to_shared(Vl);
    const unsigned ph_b = (unsigned)__cvta_generic_to_shared(Ph);
    const unsigned pl_b = (unsigned)__cvta_generic_to_shared(Pl);

    const size_t rs = QKV_COLS;
    const size_t qoff = (size_t)(b * S_LEN + qt * 64) * rs + h * HD;

#pragma unroll
    for (int i = 0; i < 2; i++) {
        int idx = i * 256 + t;
        int r = idx >> 3, c8 = (idx & 7) << 3;
        float4 vh4 = *(const float4*)(qkvh + qoff + (size_t)r * rs + c8);
        float4 vl4 = *(const float4*)(qkvl + qoff + (size_t)r * rs + c8);
        *(float4*)&Qh[r * QP + c8] = vh4;
        *(float4*)&Ql[r * QP + c8] = vl4;
    }
    if (t < 64) { mrow[t] = -1e30f; lrow[t] = 0.f; }

    float o[4][4];
#pragma unroll
    for (int i = 0; i < 4; i++)
#pragma unroll
        for (int j = 0; j < 4; j++) o[i][j] = 0.f;

    for (int kt = 0; kt <= qt; kt++) {
        const size_t koff = (size_t)(b * S_LEN + kt * 64) * rs + D_MODEL + h * HD;
        const size_t voff = koff + D_MODEL;
#pragma unroll
        for (int i = 0; i < 2; i++) {
            int idx = i * 256 + t;
            int r = idx >> 3, c8 = (idx & 7) << 3;
            float4 a = *(const float4*)(qkvh + koff + (size_t)r * rs + c8);
            float4 c = *(const float4*)(qkvl + koff + (size_t)r * rs + c8);
            float4 d = *(const float4*)(qkvh + voff + (size_t)r * rs + c8);
            float4 e = *(const float4*)(qkvl + voff + (size_t)r * rs + c8);
            *(float4*)&Kh[r * QP + c8] = a;
            *(float4*)&Kl[r * QP + c8] = c;
            *(float4*)&Vh[r * QP + c8] = d;
            *(float4*)&Vl[r * QP + c8] = e;
        }
        __syncthreads();

        // S = Q K^T, term-major per k-chunk
        float sa[4][4];
#pragma unroll
        for (int i = 0; i < 4; i++)
#pragma unroll
            for (int j = 0; j < 4; j++) sa[i][j] = 0.f;

#pragma unroll
        for (int kc = 0; kc < 64; kc += 16) {
            unsigned aH[4], aL[4], bH[4][2], bL[4][2];
            const unsigned aoff =
                (unsigned)(((wm << 4) + (lane & 15)) * (QP * 2) + (kc + ((lane >> 4) << 3)) * 2);
            ldsm_x4(aH, qh_b + aoff);
            ldsm_x4(aL, ql_b + aoff);
#pragma unroll
            for (int nt = 0; nt < 4; nt++) {
                const int nb = (wn << 5) + (nt << 3);
                const unsigned boff =
                    (unsigned)((nb + (lane & 7)) * (QP * 2) + (kc + (((lane >> 3) & 1) << 3)) * 2);
                ldsm_x2(bH[nt], kh_b + boff);
                ldsm_x2(bL[nt], kl_b + boff);
            }
#pragma unroll
            for (int nt = 0; nt < 4; nt++)
                mma_bf16(sa[nt], aH[0], aH[1], aH[2], aH[3], bH[nt][0], bH[nt][1]);
#pragma unroll
            for (int nt = 0; nt < 4; nt++)
                mma_bf16(sa[nt], aL[0], aL[1], aL[2], aL[3], bH[nt][0], bH[nt][1]);
#pragma unroll
            for (int nt = 0; nt < 4; nt++)
                mma_bf16(sa[nt], aH[0], aH[1], aH[2], aH[3], bL[nt][0], bL[nt][1]);
        }

        {
            const bool diag = (kt == qt);
            const int r0l = (wm << 4) + g;
            const int r1l = r0l + 8;
#pragma unroll
            for (int nt = 0; nt < 4; nt++) {
                const int cb = (wn << 5) + (nt << 3) + (tig << 1);
                float v0 = sa[nt][0] * 0.125f;
                float v1 = sa[nt][1] * 0.125f;
                float v2 = sa[nt][2] * 0.125f;
                float v3 = sa[nt][3] * 0.125f;
                if (diag) {
                    if (cb     > r0l) v0 = -1e30f;
                    if (cb + 1 > r0l) v1 = -1e30f;
                    if (cb     > r1l) v2 = -1e30f;
                    if (cb + 1 > r1l) v3 = -1e30f;
                }
                float2 w0 = {v0, v1}, w1 = {v2, v3};
                *(float2*)&Ss[r0l * 68 + cb] = w0;
                *(float2*)&Ss[r1l * 68 + cb] = w1;
            }
        }
        __syncthreads();

        // online softmax, emit split P
        {
            const int r  = t >> 2;
            const int qq = t & 3;
            float* srow = &Ss[r * 68 + qq * 16];
            float4 v0 = *(float4*)&srow[0];
            float4 v1 = *(float4*)&srow[4];
            float4 v2 = *(float4*)&srow[8];
            float4 v3 = *(float4*)&srow[12];
            float mloc = fmaxf(fmaxf(fmaxf(v0.x, v0.y), fmaxf(v0.z, v0.w)),
                               fmaxf(fmaxf(v1.x, v1.y), fmaxf(v1.z, v1.w)));
            mloc = fmaxf(mloc, fmaxf(fmaxf(v2.x, v2.y), fmaxf(v2.z, v2.w)));
            mloc = fmaxf(mloc, fmaxf(fmaxf(v3.x, v3.y), fmaxf(v3.z, v3.w)));
            mloc = fmaxf(mloc, __shfl_xor_sync(0xffffffffu, mloc, 1));
            mloc = fmaxf(mloc, __shfl_xor_sync(0xffffffffu, mloc, 2));
            float mold = mrow[r];
            float mnew = fmaxf(mold, mloc);

            float p[16];
            p[0]  = __expf(v0.x - mnew); p[1]  = __expf(v0.y - mnew);
            p[2]  = __expf(v0.z - mnew); p[3]  = __expf(v0.w - mnew);
            p[4]  = __expf(v1.x - mnew); p[5]  = __expf(v1.y - mnew);
            p[6]  = __expf(v1.z - mnew); p[7]  = __expf(v1.w - mnew);
            p[8]  = __expf(v2.x - mnew); p[9]  = __expf(v2.y - mnew);
            p[10] = __expf(v2.z - mnew); p[11] = __expf(v2.w - mnew);
            p[12] = __expf(v3.x - mnew); p[13] = __expf(v3.y - mnew);
            p[14] = __expf(v3.z - mnew); p[15] = __expf(v3.w - mnew);

            float lsum = 0.f;
#pragma unroll
            for (int e = 0; e < 16; e++) lsum += p[e];

            const int cbase = r * QP + qq * 16;
#pragma unroll
            for (int e = 0; e < 16; e += 4) {
                float4 pv = {p[e], p[e + 1], p[e + 2], p[e + 3]};
                unsigned h01, h23, l01, l23;
                split4(pv, h01, h23, l01, l23);
                *reinterpret_cast<unsigned*>(&Ph[cbase + e])     = h01;
                *reinterpret_cast<unsigned*>(&Ph[cbase + e + 2]) = h23;
                *reinterpret_cast<unsigned*>(&Pl[cbase + e])     = l01;
                *reinterpret_cast<unsigned*>(&Pl[cbase + e + 2]) = l23;
            }

            lsum += __shfl_xor_sync(0xffffffffu, lsum, 1);
            lsum += __shfl_xor_sync(0xffffffffu, lsum, 2);
            if (qq == 0) {
                float alpha = __expf(mold - mnew);
                lrow[r] = lrow[r] * alpha + lsum;
                mrow[r] = mnew;
                alph[r] = alpha;
            }
        }
        __syncthreads();

        // O = O*alpha + P V, term-major per k-chunk
        {
            const float a0 = alph[(wm << 4) + g];
            const float a1 = alph[(wm << 4) + g + 8];
#pragma unroll
            for (int nt = 0; nt < 4; nt++) {
                o[nt][0] *= a0; o[nt][1] *= a0;
                o[nt][2] *= a1; o[nt][3] *= a1;
            }
#pragma unroll
            for (int kc = 0; kc < 64; kc += 16) {
                unsigned pH[4], pL[4], vH[4][2], vL[4][2];
                const unsigned poff =
                    (unsigned)(((wm << 4) + (lane & 15)) * (QP * 2) + (kc + ((lane >> 4) << 3)) * 2);
                ldsm_x4(pH, ph_b + poff);
                ldsm_x4(pL, pl_b + poff);
#pragma unroll
                for (int nt = 0; nt < 4; nt++) {
                    const int nb = (wn << 5) + (nt << 3);
                    const unsigned voff2 =
                        (unsigned)((kc + (lane & 15)) * (QP * 2) + nb * 2);
                    ldsm_x2t(vH[nt], vh_b + voff2);
                    ldsm_x2t(vL[nt], vl_b + voff2);
                }
#pragma unroll
                for (int nt = 0; nt < 4; nt++)
                    mma_bf16(o[nt], pH[0], pH[1], pH[2], pH[3], vH[nt][0], vH[nt][1]);
#pragma unroll
                for (int nt = 0; nt < 4; nt++)
                    mma_bf16(o[nt], pL[0], pL[1], pL[2], pL[3], vH[nt][0], vH[nt][1]);
#pragma unroll
                for (int nt = 0; nt < 4; nt++)
                    mma_bf16(o[nt], pH[0], pH[1], pH[2], pH[3], vL[nt][0], vL[nt][1]);
            }
        }
        __syncthreads();
    }

    // Epilogue: divide by l, write split z
    {
        const float l0 = 1.f / lrow[(wm << 4) + g];
        const float l1 = 1.f / lrow[(wm << 4) + g + 8];
        const int row0 = qt * 64 + (wm << 4) + g;
        const int row1 = row0 + 8;
#pragma unroll
        for (int nt = 0; nt < 4; nt++) {
            const int col = (wn << 5) + (nt << 3) + (tig << 1);
            float w00 = o[nt][0] * l0, w01 = o[nt][1] * l0;
            float w10 = o[nt][2] * l1, w11 = o[nt][3] * l1;
            __nv_bfloat16 h00 = __float2bfloat16_rn(w00);
            __nv_bfloat16 h01 = __float2bfloat16_rn(w01);
            __nv_bfloat16 h10 = __float2bfloat16_rn(w10);
            __nv_bfloat16 h11 = __float2bfloat16_rn(w11);
            float l00 = w00 - __bfloat162float(h00);
            float l01v = w01 - __bfloat162float(h01);
            float l10 = w10 - __bfloat162float(h10);
            float l11 = w11 - __bfloat162float(h11);
            size_t o0 = (size_t)(b * S_LEN + row0) * D_MODEL + h * HD + col;
            size_t o1 = (size_t)(b * S_LEN + row1) * D_MODEL + h * HD + col;
            __nv_bfloat162 t0 = {h00, h01};
            __nv_bfloat162 t1 = {h10, h11};
            *reinterpret_cast<unsigned*>(zh + o0) = *reinterpret_cast<unsigned*>(&t0);
            *reinterpret_cast<unsigned*>(zh + o1) = *reinterpret_cast<unsigned*>(&t1);
            *reinterpret_cast<unsigned*>(zl + o0) = pack_bf2(l00, l01v);
            *reinterpret_cast<unsigned*>(zl + o1) = pack_bf2(l10, l11);
        }
    }
}

// ---------------------------------------------------------------------------
extern "C" void kernel_launch(void* const* d_in, const int* in_sizes, int n_in,
                              void* d_out, int out_size)
{
    const float* x     = (const float*)d_in[0];
    const float* w_qkv = (const float*)d_in[1];
    const float* b_qkv = (const float*)d_in[2];
    const float* w_out = (const float*)d_in[3];
    const float* b_out = (const float*)d_in[4];
    float* out = (float*)d_out;

    __nv_bfloat16 *xh, *xl, *wqh, *wql, *woh, *wol, *qkvh, *qkvl, *zh, *zl;
    cudaGetSymbolAddress((void**)&xh, g_xh);
    cudaGetSymbolAddress((void**)&xl, g_xl);
    cudaGetSymbolAddress((void**)&wqh, g_wqh);
    cudaGetSymbolAddress((void**)&wql, g_wql);
    cudaGetSymbolAddress((void**)&woh, g_woh);
    cudaGetSymbolAddress((void**)&wol, g_wol);
    cudaGetSymbolAddress((void**)&qkvh, g_qkvh);
    cudaGetSymbolAddress((void**)&qkvl, g_qkvl);
    cudaGetSymbolAddress((void**)&zh, g_zh);
    cudaGetSymbolAddress((void**)&zl, g_zl);

    cudaFuncSetAttribute(gemm_bf16pre_kernel,
                         cudaFuncAttributeMaxDynamicSharedMemorySize,
                         GEMM_SMEM_BYTES);
    cudaFuncSetAttribute(attn_mma_kernel,
                         cudaFuncAttributeMaxDynamicSharedMemorySize,
                         ATT2_SMEM_BYTES);

    // 0) split inputs/weights to bf16 hi/lo
    {
        int n;
        n = M_ROWS * D_MODEL / 4;
        split_kernel<<<(n + 255) / 256, 256>>>(x, xh, xl, n);
        n = D_MODEL * QKV_COLS / 4;
        split_kernel<<<(n + 255) / 256, 256>>>(w_qkv, wqh, wql, n);
        n = D_MODEL * D_MODEL / 4;
        split_kernel<<<(n + 255) / 256, 256>>>(w_out, woh, wol, n);
    }
    // 1) QKV GEMM -> split bf16 qkv
    {
        dim3 grid(QKV_COLS / 128, M_ROWS / 128);
        gemm_bf16pre_kernel<<<grid, 256, GEMM_SMEM_BYTES>>>(
            xh, xl, wqh, wql, b_qkv, nullptr, qkvh, qkvl,
            M_ROWS, QKV_COLS, D_MODEL, 1);
    }
    // 2) attention -> split bf16 z
    {
        dim3 grid(S_LEN / 64, B_SZ * NH);
        attn_mma_kernel<<<grid, 256, ATT2_SMEM_BYTES>>>(qkvh, qkvl, zh, zl);
    }
    // 3) out GEMM -> fp32 output
    {
        dim3 grid(D_MODEL / 128, M_ROWS / 128);
        gemm_bf16pre_kernel<<<grid, 256, GEMM_SMEM_BYTES>>>(
            zh, zl, woh, wol, b_out, out, nullptr, nullptr,
            M_ROWS, D_MODEL, D_MODEL, 0);
    }
}

// round 15
// speedup vs baseline: 2.8673x; 1.1555x over previous
#include <cuda_runtime.h>
#include <cuda_bf16.h>
#include <cuda_fp16.h>
#include <math.h>

#define S_LEN 2048
#define B_SZ 2
#define D_MODEL 1024
#define NH 16
#define HD 64
#define M_ROWS 4096
#define QKV_COLS 3072

// fp16 split activations / weights (GEMM path), bf16 split qkv (attention path)
__device__ __half g_xh[(size_t)M_ROWS * D_MODEL];
__device__ __half g_xl[(size_t)M_ROWS * D_MODEL];
__device__ __half g_wqh[(size_t)D_MODEL * QKV_COLS];
__device__ __half g_woh[(size_t)D_MODEL * D_MODEL];
__device__ __nv_bfloat16 g_qkvh[(size_t)M_ROWS * QKV_COLS];
__device__ __nv_bfloat16 g_qkvl[(size_t)M_ROWS * QKV_COLS];
__device__ __half g_zh[(size_t)M_ROWS * D_MODEL];
__device__ __half g_zl[(size_t)M_ROWS * D_MODEL];

// ---------------------------------------------------------------------------
// helpers
// ---------------------------------------------------------------------------
__device__ __forceinline__ unsigned pack_bf2(float x, float y) {
    __nv_bfloat162 h = __floats2bfloat162_rn(x, y);
    return *reinterpret_cast<unsigned*>(&h);
}
__device__ __forceinline__ unsigned pack_hf2(float x, float y) {
    __half2 h = __floats2half2_rn(x, y);
    return *reinterpret_cast<unsigned*>(&h);
}

__device__ __forceinline__ void mma_bf16(float* c,
                                         unsigned a0, unsigned a1,
                                         unsigned a2, unsigned a3,
                                         unsigned b0, unsigned b1) {
    asm volatile(
        "mma.sync.aligned.m16n8k16.row.col.f32.bf16.bf16.f32 "
        "{%0,%1,%2,%3}, {%4,%5,%6,%7}, {%8,%9}, {%0,%1,%2,%3};\n"
        : "+f"(c[0]), "+f"(c[1]), "+f"(c[2]), "+f"(c[3])
        : "r"(a0), "r"(a1), "r"(a2), "r"(a3), "r"(b0), "r"(b1));
}
__device__ __forceinline__ void mma_f16(float* c,
                                        unsigned a0, unsigned a1,
                                        unsigned a2, unsigned a3,
                                        unsigned b0, unsigned b1) {
    asm volatile(
        "mma.sync.aligned.m16n8k16.row.col.f32.f16.f16.f32 "
        "{%0,%1,%2,%3}, {%4,%5,%6,%7}, {%8,%9}, {%0,%1,%2,%3};\n"
        : "+f"(c[0]), "+f"(c[1]), "+f"(c[2]), "+f"(c[3])
        : "r"(a0), "r"(a1), "r"(a2), "r"(a3), "r"(b0), "r"(b1));
}

__device__ __forceinline__ void ldsm_x4(unsigned r[4], unsigned addr) {
    asm volatile("ldmatrix.sync.aligned.m8n8.x4.shared.b16 {%0,%1,%2,%3}, [%4];"
                 : "=r"(r[0]), "=r"(r[1]), "=r"(r[2]), "=r"(r[3]) : "r"(addr));
}
__device__ __forceinline__ void ldsm_x2(unsigned r[2], unsigned addr) {
    asm volatile("ldmatrix.sync.aligned.m8n8.x2.shared.b16 {%0,%1}, [%2];"
                 : "=r"(r[0]), "=r"(r[1]) : "r"(addr));
}
__device__ __forceinline__ void ldsm_x2t(unsigned r[2], unsigned addr) {
    asm volatile("ldmatrix.sync.aligned.m8n8.x2.trans.shared.b16 {%0,%1}, [%2];"
                 : "=r"(r[0]), "=r"(r[1]) : "r"(addr));
}

// bf16 hi/lo split of a float4 (attention path)
__device__ __forceinline__ void split4(float4 v,
                                       unsigned& h01, unsigned& h23,
                                       unsigned& l01, unsigned& l23) {
    float f[4] = {v.x, v.y, v.z, v.w};
    float hi[4], lo[4];
#pragma unroll
    for (int e = 0; e < 4; e++) {
        __nv_bfloat16 h = __float2bfloat16_rn(f[e]);
        hi[e] = __bfloat162float(h);
        lo[e] = f[e] - hi[e];
    }
    h01 = pack_bf2(hi[0], hi[1]); h23 = pack_bf2(hi[2], hi[3]);
    l01 = pack_bf2(lo[0], lo[1]); l23 = pack_bf2(lo[2], lo[3]);
}

// fp16 hi/lo split of a float4 (GEMM path)
__device__ __forceinline__ void split4h(float4 v,
                                        unsigned& h01, unsigned& h23,
                                        unsigned& l01, unsigned& l23) {
    float f[4] = {v.x, v.y, v.z, v.w};
    float hi[4], lo[4];
#pragma unroll
    for (int e = 0; e < 4; e++) {
        __half h = __float2half_rn(f[e]);
        hi[e] = __half2float(h);
        lo[e] = f[e] - hi[e];
    }
    h01 = pack_hf2(hi[0], hi[1]); h23 = pack_hf2(hi[2], hi[3]);
    l01 = pack_hf2(lo[0], lo[1]); l23 = pack_hf2(lo[2], lo[3]);
}

__device__ __forceinline__ void cp16(unsigned dst, const void* src) {
    asm volatile("cp.async.cg.shared.global [%0], [%1], 16;\n" :: "r"(dst), "l"(src));
}
#define CP_COMMIT() asm volatile("cp.async.commit_group;\n")
#define CP_WAIT1()  asm volatile("cp.async.wait_group 1;\n")

// ---------------------------------------------------------------------------
// prep kernels
// ---------------------------------------------------------------------------
__global__ void splith_kernel(const float* __restrict__ src,
                              __half* __restrict__ h,
                              __half* __restrict__ l, int n4)
{
    int i = blockIdx.x * blockDim.x + threadIdx.x;
    if (i < n4) {
        float4 v = reinterpret_cast<const float4*>(src)[i];
        unsigned h01, h23, l01, l23;
        split4h(v, h01, h23, l01, l23);
        reinterpret_cast<unsigned*>(h)[i * 2]     = h01;
        reinterpret_cast<unsigned*>(h)[i * 2 + 1] = h23;
        reinterpret_cast<unsigned*>(l)[i * 2]     = l01;
        reinterpret_cast<unsigned*>(l)[i * 2 + 1] = l23;
    }
}

__global__ void tof16_kernel(const float* __restrict__ src,
                             __half* __restrict__ h, int n4)
{
    int i = blockIdx.x * blockDim.x + threadIdx.x;
    if (i < n4) {
        float4 v = reinterpret_cast<const float4*>(src)[i];
        reinterpret_cast<unsigned*>(h)[i * 2]     = pack_hf2(v.x, v.y);
        reinterpret_cast<unsigned*>(h)[i * 2 + 1] = pack_hf2(v.z, v.w);
    }
}

// ---------------------------------------------------------------------------
// fp16 2-term tensor-core GEMM: C = (Ah + Al) @ fp16(W) + bias  (== A @ Wh)
// A: fp16 hi/lo [M][K]; W: fp16 [K][N]. cp.async double-buffered, BK=32,
// 8 warps (2x4), warp tile 64x32, m16n8k16. Out: fp32 or split-bf16.
// ---------------------------------------------------------------------------
#define AP 40
#define WP 136
#define AS (128 * AP)
#define WS (32 * WP)
#define STG2 (2 * AS + WS)
#define GEMM_SMEM_BYTES (2 * STG2 * 2)

__global__ __launch_bounds__(256, 2) void gemm_f16_2t_kernel(
    const __half* __restrict__ Ahg, const __half* __restrict__ Alg,
    const __half* __restrict__ Whg,
    const float* __restrict__ bias,
    float* __restrict__ Cf,
    __nv_bfloat16* __restrict__ Ch, __nv_bfloat16* __restrict__ Cl,
    int M, int N, int K, int splitOut)
{
    extern __shared__ __half smg[];
    const unsigned sbase = (unsigned)__cvta_generic_to_shared(smg);

    const int t    = threadIdx.x;
    const int lane = t & 31;
    const int warp = t >> 5;
    const int g    = lane >> 2;
    const int tig  = lane & 3;
    const int wm   = warp >> 2;
    const int wn   = warp & 3;
    const int m0   = blockIdx.y << 7;
    const int n0   = blockIdx.x << 7;

    float acc[4][4][4];
#pragma unroll
    for (int i = 0; i < 4; i++)
#pragma unroll
        for (int j = 0; j < 4; j++)
#pragma unroll
            for (int r = 0; r < 4; r++) acc[i][j][r] = 0.f;

    auto issue = [&](int it, int stg) {
        const int k0 = it << 5;
        const unsigned base = sbase + (unsigned)(stg * STG2 * 2);
#pragma unroll
        for (int c = t; c < 512; c += 256) {
            const int row = c >> 2, off = (c & 3) << 3;
            const size_t s = (size_t)(m0 + row) * K + k0 + off;
            cp16(base + (unsigned)((row * AP + off) * 2), Ahg + s);
            cp16(base + (unsigned)((AS + row * AP + off) * 2), Alg + s);
        }
#pragma unroll
        for (int c = t; c < 512; c += 256) {
            const int row = c >> 4, off = (c & 15) << 3;
            const size_t s = (size_t)(k0 + row) * N + n0 + off;
            cp16(base + (unsigned)((2 * AS + row * WP + off) * 2), Whg + s);
        }
    };

    issue(0, 0);
    CP_COMMIT();

    const int NIT = K >> 5;
    for (int it = 0; it < NIT; it++) {
        if (it + 1 < NIT) issue(it + 1, (it + 1) & 1);
        CP_COMMIT();
        CP_WAIT1();
        __syncthreads();

        const unsigned ah_b = sbase + (unsigned)((it & 1) * STG2 * 2);
        const unsigned al_b = ah_b + AS * 2;
        const unsigned wh_b = ah_b + 2 * AS * 2;

#pragma unroll
        for (int kc = 0; kc < 32; kc += 16) {
            unsigned ahi[4][4], alo[4][4], bh[4][2];
#pragma unroll
            for (int mt = 0; mt < 4; mt++) {
                const int row = (wm << 6) + (mt << 4) + (lane & 15);
                const int col = kc + ((lane >> 4) << 3);
                const unsigned off = (unsigned)(row * (AP * 2) + col * 2);
                ldsm_x4(ahi[mt], ah_b + off);
                ldsm_x4(alo[mt], al_b + off);
            }
#pragma unroll
            for (int nt = 0; nt < 4; nt++) {
                const int krow = kc + (lane & 15);
                const int ncol = (wn << 5) + (nt << 3);
                const unsigned off = (unsigned)(krow * (WP * 2) + ncol * 2);
                ldsm_x2t(bh[nt], wh_b + off);
            }
#pragma unroll
            for (int mt = 0; mt < 4; mt++)
#pragma unroll
                for (int nt = 0; nt < 4; nt++)
                    mma_f16(acc[mt][nt], ahi[mt][0], ahi[mt][1], ahi[mt][2], ahi[mt][3],
                            bh[nt][0], bh[nt][1]);
#pragma unroll
            for (int mt = 0; mt < 4; mt++)
#pragma unroll
                for (int nt = 0; nt < 4; nt++)
                    mma_f16(acc[mt][nt], alo[mt][0], alo[mt][1], alo[mt][2], alo[mt][3],
                            bh[nt][0], bh[nt][1]);
        }
        __syncthreads();
    }

    // Epilogue
#pragma unroll
    for (int mt = 0; mt < 4; mt++) {
        const int row0 = m0 + (wm << 6) + (mt << 4) + g;
        const int row1 = row0 + 8;
#pragma unroll
        for (int nt = 0; nt < 4; nt++) {
            const int col = n0 + (wn << 5) + (nt << 3) + (tig << 1);
            const float b0 = bias[col];
            const float b1 = bias[col + 1];
            float v00 = acc[mt][nt][0] + b0, v01 = acc[mt][nt][1] + b1;
            float v10 = acc[mt][nt][2] + b0, v11 = acc[mt][nt][3] + b1;
            if (!splitOut) {
                float2 w0 = {v00, v01}, w1 = {v10, v11};
                *(float2*)(Cf + (size_t)row0 * N + col) = w0;
                *(float2*)(Cf + (size_t)row1 * N + col) = w1;
            } else {
                __nv_bfloat16 h00 = __float2bfloat16_rn(v00);
                __nv_bfloat16 h01 = __float2bfloat16_rn(v01);
                __nv_bfloat16 h10 = __float2bfloat16_rn(v10);
                __nv_bfloat16 h11 = __float2bfloat16_rn(v11);
                float l00 = v00 - __bfloat162float(h00);
                float l01 = v01 - __bfloat162float(h01);
                float l10 = v10 - __bfloat162float(h10);
                float l11 = v11 - __bfloat162float(h11);
                __nv_bfloat162 t0 = {h00, h01};
                __nv_bfloat162 t1 = {h10, h11};
                *reinterpret_cast<unsigned*>(Ch + (size_t)row0 * N + col) =
                    *reinterpret_cast<unsigned*>(&t0);
                *reinterpret_cast<unsigned*>(Ch + (size_t)row1 * N + col) =
                    *reinterpret_cast<unsigned*>(&t1);
                *reinterpret_cast<unsigned*>(Cl + (size_t)row0 * N + col) = pack_bf2(l00, l01);
                *reinterpret_cast<unsigned*>(Cl + (size_t)row1 * N + col) = pack_bf2(l10, l11);
            }
        }
    }
}

// ---------------------------------------------------------------------------
// Flash attention (causal), bf16 3-term split MMA (verified); emits fp16 z.
// ---------------------------------------------------------------------------
#define QP 72
#define ATT2_SMEM_BYTES (8 * 64 * QP * 2 + 64 * 68 * 4 + 3 * 64 * 4)

__global__ __launch_bounds__(256) void attn_mma_kernel(
    const __nv_bfloat16* __restrict__ qkvh, const __nv_bfloat16* __restrict__ qkvl,
    __half* __restrict__ zh, __half* __restrict__ zl)
{
    extern __shared__ char smraw[];
    __nv_bfloat16* Qh = (__nv_bfloat16*)smraw;
    __nv_bfloat16* Ql = Qh + 64 * QP;
    __nv_bfloat16* Kh = Ql + 64 * QP;
    __nv_bfloat16* Kl = Kh + 64 * QP;
    __nv_bfloat16* Vh = Kl + 64 * QP;
    __nv_bfloat16* Vl = Vh + 64 * QP;
    __nv_bfloat16* Ph = Vl + 64 * QP;
    __nv_bfloat16* Pl = Ph + 64 * QP;
    float* Ss   = (float*)(Pl + 64 * QP);
    float* mrow = Ss + 64 * 68;
    float* lrow = mrow + 64;
    float* alph = lrow + 64;

    const int t    = threadIdx.x;
    const int lane = t & 31;
    const int warp = t >> 5;
    const int g    = lane >> 2;
    const int tig  = lane & 3;
    const int wm   = warp >> 1;
    const int wn   = warp & 1;
    const int qt   = (S_LEN / 64 - 1) - blockIdx.x;
    const int bh   = blockIdx.y;
    const int b    = bh >> 4;
    const int h    = bh & 15;

    const unsigned qh_b = (unsigned)__cvta_generic_to_shared(Qh);
    const unsigned ql_b = (unsigned)__cvta_generic_to_shared(Ql);
    const unsigned kh_b = (unsigned)__cvta_generic_to_shared(Kh);
    const unsigned kl_b = (unsigned)__cvta_generic_to_shared(Kl);
    const unsigned vh_b = (unsigned)__cvta_generic_to_shared(Vh);
    const unsigned vl_b = (unsigned)__cvta_generic_to_shared(Vl);
    const unsigned ph_b = (unsigned)__cvta_generic_to_shared(Ph);
    const unsigned pl_b = (unsigned)__cvta_generic_to_shared(Pl);

    const size_t rs = QKV_COLS;
    const size_t qoff = (size_t)(b * S_LEN + qt * 64) * rs + h * HD;

#pragma unroll
    for (int i = 0; i < 2; i++) {
        int idx = i * 256 + t;
        int r = idx >> 3, c8 = (idx & 7) << 3;
        float4 vh4 = *(const float4*)(qkvh + qoff + (size_t)r * rs + c8);
        float4 vl4 = *(const float4*)(qkvl + qoff + (size_t)r * rs + c8);
        *(float4*)&Qh[r * QP + c8] = vh4;
        *(float4*)&Ql[r * QP + c8] = vl4;
    }
    if (t < 64) { mrow[t] = -1e30f; lrow[t] = 0.f; }

    float o[4][4];
#pragma unroll
    for (int i = 0; i < 4; i++)
#pragma unroll
        for (int j = 0; j < 4; j++) o[i][j] = 0.f;

    for (int kt = 0; kt <= qt; kt++) {
        const size_t koff = (size_t)(b * S_LEN + kt * 64) * rs + D_MODEL + h * HD;
        const size_t voff = koff + D_MODEL;
#pragma unroll
        for (int i = 0; i < 2; i++) {
            int idx = i * 256 + t;
            int r = idx >> 3, c8 = (idx & 7) << 3;
            float4 a = *(const float4*)(qkvh + koff + (size_t)r * rs + c8);
            float4 c = *(const float4*)(qkvl + koff + (size_t)r * rs + c8);
            float4 d = *(const float4*)(qkvh + voff + (size_t)r * rs + c8);
            float4 e = *(const float4*)(qkvl + voff + (size_t)r * rs + c8);
            *(float4*)&Kh[r * QP + c8] = a;
            *(float4*)&Kl[r * QP + c8] = c;
            *(float4*)&Vh[r * QP + c8] = d;
            *(float4*)&Vl[r * QP + c8] = e;
        }
        __syncthreads();

        float sa[4][4];
#pragma unroll
        for (int i = 0; i < 4; i++)
#pragma unroll
            for (int j = 0; j < 4; j++) sa[i][j] = 0.f;

#pragma unroll
        for (int kc = 0; kc < 64; kc += 16) {
            unsigned aH[4], aL[4], bH[4][2], bL[4][2];
            const unsigned aoff =
                (unsigned)(((wm << 4) + (lane & 15)) * (QP * 2) + (kc + ((lane >> 4) << 3)) * 2);
            ldsm_x4(aH, qh_b + aoff);
            ldsm_x4(aL, ql_b + aoff);
#pragma unroll
            for (int nt = 0; nt < 4; nt++) {
                const int nb = (wn << 5) + (nt << 3);
                const unsigned boff =
                    (unsigned)((nb + (lane & 7)) * (QP * 2) + (kc + (((lane >> 3) & 1) << 3)) * 2);
                ldsm_x2(bH[nt], kh_b + boff);
                ldsm_x2(bL[nt], kl_b + boff);
            }
#pragma unroll
            for (int nt = 0; nt < 4; nt++)
                mma_bf16(sa[nt], aH[0], aH[1], aH[2], aH[3], bH[nt][0], bH[nt][1]);
#pragma unroll
            for (int nt = 0; nt < 4; nt++)
                mma_bf16(sa[nt], aL[0], aL[1], aL[2], aL[3], bH[nt][0], bH[nt][1]);
#pragma unroll
            for (int nt = 0; nt < 4; nt++)
                mma_bf16(sa[nt], aH[0], aH[1], aH[2], aH[3], bL[nt][0], bL[nt][1]);
        }

        {
            const bool diag = (kt == qt);
            const int r0l = (wm << 4) + g;
            const int r1l = r0l + 8;
#pragma unroll
            for (int nt = 0; nt < 4; nt++) {
                const int cb = (wn << 5) + (nt << 3) + (tig << 1);
                float v0 = sa[nt][0] * 0.125f;
                float v1 = sa[nt][1] * 0.125f;
                float v2 = sa[nt][2] * 0.125f;
                float v3 = sa[nt][3] * 0.125f;
                if (diag) {
                    if (cb     > r0l) v0 = -1e30f;
                    if (cb + 1 > r0l) v1 = -1e30f;
                    if (cb     > r1l) v2 = -1e30f;
                    if (cb + 1 > r1l) v3 = -1e30f;
                }
                float2 w0 = {v0, v1}, w1 = {v2, v3};
                *(float2*)&Ss[r0l * 68 + cb] = w0;
                *(float2*)&Ss[r1l * 68 + cb] = w1;
            }
        }
        __syncthreads();

        {
            const int r  = t >> 2;
            const int qq = t & 3;
            float* srow = &Ss[r * 68 + qq * 16];
            float4 v0 = *(float4*)&srow[0];
            float4 v1 = *(float4*)&srow[4];
            float4 v2 = *(float4*)&srow[8];
            float4 v3 = *(float4*)&srow[12];
            float mloc = fmaxf(fmaxf(fmaxf(v0.x, v0.y), fmaxf(v0.z, v0.w)),
                               fmaxf(fmaxf(v1.x, v1.y), fmaxf(v1.z, v1.w)));
            mloc = fmaxf(mloc, fmaxf(fmaxf(v2.x, v2.y), fmaxf(v2.z, v2.w)));
            mloc = fmaxf(mloc, fmaxf(fmaxf(v3.x, v3.y), fmaxf(v3.z, v3.w)));
            mloc = fmaxf(mloc, __shfl_xor_sync(0xffffffffu, mloc, 1));
            mloc = fmaxf(mloc, __shfl_xor_sync(0xffffffffu, mloc, 2));
            float mold = mrow[r];
            float mnew = fmaxf(mold, mloc);

            float p[16];
            p[0]  = __expf(v0.x - mnew); p[1]  = __expf(v0.y - mnew);
            p[2]  = __expf(v0.z - mnew); p[3]  = __expf(v0.w - mnew);
            p[4]  = __expf(v1.x - mnew); p[5]  = __expf(v1.y - mnew);
            p[6]  = __expf(v1.z - mnew); p[7]  = __expf(v1.w - mnew);
            p[8]  = __expf(v2.x - mnew); p[9]  = __expf(v2.y - mnew);
            p[10] = __expf(v2.z - mnew); p[11] = __expf(v2.w - mnew);
            p[12] = __expf(v3.x - mnew); p[13] = __expf(v3.y - mnew);
            p[14] = __expf(v3.z - mnew); p[15] = __expf(v3.w - mnew);

            float lsum = 0.f;
#pragma unroll
            for (int e = 0; e < 16; e++) lsum += p[e];

            const int cbase = r * QP + qq * 16;
#pragma unroll
            for (int e = 0; e < 16; e += 4) {
                float4 pv = {p[e], p[e + 1], p[e + 2], p[e + 3]};
                unsigned h01, h23, l01, l23;
                split4(pv, h01, h23, l01, l23);
                *reinterpret_cast<unsigned*>(&Ph[cbase + e])     = h01;
                *reinterpret_cast<unsigned*>(&Ph[cbase + e + 2]) = h23;
                *reinterpret_cast<unsigned*>(&Pl[cbase + e])     = l01;
                *reinterpret_cast<unsigned*>(&Pl[cbase + e + 2]) = l23;
            }

            lsum += __shfl_xor_sync(0xffffffffu, lsum, 1);
            lsum += __shfl_xor_sync(0xffffffffu, lsum, 2);
            if (qq == 0) {
                float alpha = __expf(mold - mnew);
                lrow[r] = lrow[r] * alpha + lsum;
                mrow[r] = mnew;
                alph[r] = alpha;
            }
        }
        __syncthreads();

        {
            const float a0 = alph[(wm << 4) + g];
            const float a1 = alph[(wm << 4) + g + 8];
#pragma unroll
            for (int nt = 0; nt < 4; nt++) {
                o[nt][0] *= a0; o[nt][1] *= a0;
                o[nt][2] *= a1; o[nt][3] *= a1;
            }
#pragma unroll
            for (int kc = 0; kc < 64; kc += 16) {
                unsigned pH[4], pL[4], vH[4][2], vL[4][2];
                const unsigned poff =
                    (unsigned)(((wm << 4) + (lane & 15)) * (QP * 2) + (kc + ((lane >> 4) << 3)) * 2);
                ldsm_x4(pH, ph_b + poff);
                ldsm_x4(pL, pl_b + poff);
#pragma unroll
                for (int nt = 0; nt < 4; nt++) {
                    const int nb = (wn << 5) + (nt << 3);
                    const unsigned voff2 =
                        (unsigned)((kc + (lane & 15)) * (QP * 2) + nb * 2);
                    ldsm_x2t(vH[nt], vh_b + voff2);
                    ldsm_x2t(vL[nt], vl_b + voff2);
                }
#pragma unroll
                for (int nt = 0; nt < 4; nt++)
                    mma_bf16(o[nt], pH[0], pH[1], pH[2], pH[3], vH[nt][0], vH[nt][1]);
#pragma unroll
                for (int nt = 0; nt < 4; nt++)
                    mma_bf16(o[nt], pL[0], pL[1], pL[2], pL[3], vH[nt][0], vH[nt][1]);
#pragma unroll
                for (int nt = 0; nt < 4; nt++)
                    mma_bf16(o[nt], pH[0], pH[1], pH[2], pH[3], vL[nt][0], vL[nt][1]);
            }
        }
        __syncthreads();
    }

    // Epilogue: divide by l, write fp16 split z
    {
        const float l0 = 1.f / lrow[(wm << 4) + g];
        const float l1 = 1.f / lrow[(wm << 4) + g + 8];
        const int row0 = qt * 64 + (wm << 4) + g;
        const int row1 = row0 + 8;
#pragma unroll
        for (int nt = 0; nt < 4; nt++) {
            const int col = (wn << 5) + (nt << 3) + (tig << 1);
            float w00 = o[nt][0] * l0, w01 = o[nt][1] * l0;
            float w10 = o[nt][2] * l1, w11 = o[nt][3] * l1;
            __half h00 = __float2half_rn(w00);
            __half h01 = __float2half_rn(w01);
            __half h10 = __float2half_rn(w10);
            __half h11 = __float2half_rn(w11);
            float l00 = w00 - __half2float(h00);
            float l01v = w01 - __half2float(h01);
            float l10 = w10 - __half2float(h10);
            float l11 = w11 - __half2float(h11);
            size_t o0 = (size_t)(b * S_LEN + row0) * D_MODEL + h * HD + col;
            size_t o1 = (size_t)(b * S_LEN + row1) * D_MODEL + h * HD + col;
            __half2 t0 = {h00, h01};
            __half2 t1 = {h10, h11};
            *reinterpret_cast<unsigned*>(zh + o0) = *reinterpret_cast<unsigned*>(&t0);
            *reinterpret_cast<unsigned*>(zh + o1) = *reinterpret_cast<unsigned*>(&t1);
            *reinterpret_cast<unsigned*>(zl + o0) = pack_hf2(l00, l01v);
            *reinterpret_cast<unsigned*>(zl + o1) = pack_hf2(l10, l11);
        }
    }
}

// ---------------------------------------------------------------------------
extern "C" void kernel_launch(void* const* d_in, const int* in_sizes, int n_in,
                              void* d_out, int out_size)
{
    const float* x     = (const float*)d_in[0];
    const float* w_qkv = (const float*)d_in[1];
    const float* b_qkv = (const float*)d_in[2];
    const float* w_out = (const float*)d_in[3];
    const float* b_out = (const float*)d_in[4];
    float* out = (float*)d_out;

    __half *xh, *xl, *wqh, *woh, *zh, *zl;
    __nv_bfloat16 *qkvh, *qkvl;
    cudaGetSymbolAddress((void**)&xh, g_xh);
    cudaGetSymbolAddress((void**)&xl, g_xl);
    cudaGetSymbolAddress((void**)&wqh, g_wqh);
    cudaGetSymbolAddress((void**)&woh, g_woh);
    cudaGetSymbolAddress((void**)&qkvh, g_qkvh);
    cudaGetSymbolAddress((void**)&qkvl, g_qkvl);
    cudaGetSymbolAddress((void**)&zh, g_zh);
    cudaGetSymbolAddress((void**)&zl, g_zl);

    cudaFuncSetAttribute(gemm_f16_2t_kernel,
                         cudaFuncAttributeMaxDynamicSharedMemorySize,
                         GEMM_SMEM_BYTES);
    cudaFuncSetAttribute(attn_mma_kernel,
                         cudaFuncAttributeMaxDynamicSharedMemorySize,
                         ATT2_SMEM_BYTES);

    // 0) split x to fp16 hi/lo; convert weights to fp16
    {
        int n;
        n = M_ROWS * D_MODEL / 4;
        splith_kernel<<<(n + 255) / 256, 256>>>(x, xh, xl, n);
        n = D_MODEL * QKV_COLS / 4;
        tof16_kernel<<<(n + 255) / 256, 256>>>(w_qkv, wqh, n);
        n = D_MODEL * D_MODEL / 4;
        tof16_kernel<<<(n + 255) / 256, 256>>>(w_out, woh, n);
    }
    // 1) QKV GEMM (fp16 2-term) -> split bf16 qkv
    {
        dim3 grid(QKV_COLS / 128, M_ROWS / 128);
        gemm_f16_2t_kernel<<<grid, 256, GEMM_SMEM_BYTES>>>(
            xh, xl, wqh, b_qkv, nullptr, qkvh, qkvl,
            M_ROWS, QKV_COLS, D_MODEL, 1);
    }
    // 2) attention (bf16 3-term) -> fp16 split z
    {
        dim3 grid(S_LEN / 64, B_SZ * NH);
        attn_mma_kernel<<<grid, 256, ATT2_SMEM_BYTES>>>(qkvh, qkvl, zh, zl);
    }
    // 3) out GEMM (fp16 2-term) -> fp32 output
    {
        dim3 grid(D_MODEL / 128, M_ROWS / 128);
        gemm_f16_2t_kernel<<<grid, 256, GEMM_SMEM_BYTES>>>(
            zh, zl, woh, b_out, out, nullptr, nullptr,
            M_ROWS, D_MODEL, D_MODEL, 0);
    }
}

// round 16
// speedup vs baseline: 3.2645x; 1.1385x over previous
#include <cuda_runtime.h>
#include <cuda_bf16.h>
#include <cuda_fp16.h>
#include <math.h>

#define S_LEN 2048
#define B_SZ 2
#define D_MODEL 1024
#define NH 16
#define HD 64
#define M_ROWS 4096
#define QKV_COLS 3072

// fp16 split activations / fp16 weights
__device__ __half g_xh[(size_t)M_ROWS * D_MODEL];
__device__ __half g_xl[(size_t)M_ROWS * D_MODEL];
__device__ __half g_wqh[(size_t)D_MODEL * QKV_COLS];
__device__ __half g_woh[(size_t)D_MODEL * D_MODEL];
__device__ __half g_qkvh[(size_t)M_ROWS * QKV_COLS];
__device__ __half g_qkvl[(size_t)M_ROWS * QKV_COLS];
__device__ __half g_zh[(size_t)M_ROWS * D_MODEL];
__device__ __half g_zl[(size_t)M_ROWS * D_MODEL];

// ---------------------------------------------------------------------------
// helpers
// ---------------------------------------------------------------------------
__device__ __forceinline__ unsigned pack_hf2(float x, float y) {
    __half2 h = __floats2half2_rn(x, y);
    return *reinterpret_cast<unsigned*>(&h);
}

__device__ __forceinline__ void mma_f16(float* c,
                                        unsigned a0, unsigned a1,
                                        unsigned a2, unsigned a3,
                                        unsigned b0, unsigned b1) {
    asm volatile(
        "mma.sync.aligned.m16n8k16.row.col.f32.f16.f16.f32 "
        "{%0,%1,%2,%3}, {%4,%5,%6,%7}, {%8,%9}, {%0,%1,%2,%3};\n"
        : "+f"(c[0]), "+f"(c[1]), "+f"(c[2]), "+f"(c[3])
        : "r"(a0), "r"(a1), "r"(a2), "r"(a3), "r"(b0), "r"(b1));
}

__device__ __forceinline__ void ldsm_x4(unsigned r[4], unsigned addr) {
    asm volatile("ldmatrix.sync.aligned.m8n8.x4.shared.b16 {%0,%1,%2,%3}, [%4];"
                 : "=r"(r[0]), "=r"(r[1]), "=r"(r[2]), "=r"(r[3]) : "r"(addr));
}
__device__ __forceinline__ void ldsm_x2(unsigned r[2], unsigned addr) {
    asm volatile("ldmatrix.sync.aligned.m8n8.x2.shared.b16 {%0,%1}, [%2];"
                 : "=r"(r[0]), "=r"(r[1]) : "r"(addr));
}
__device__ __forceinline__ void ldsm_x2t(unsigned r[2], unsigned addr) {
    asm volatile("ldmatrix.sync.aligned.m8n8.x2.trans.shared.b16 {%0,%1}, [%2];"
                 : "=r"(r[0]), "=r"(r[1]) : "r"(addr));
}

// fp16 hi/lo split of a float4
__device__ __forceinline__ void split4h(float4 v,
                                        unsigned& h01, unsigned& h23,
                                        unsigned& l01, unsigned& l23) {
    float f[4] = {v.x, v.y, v.z, v.w};
    float hi[4], lo[4];
#pragma unroll
    for (int e = 0; e < 4; e++) {
        __half h = __float2half_rn(f[e]);
        hi[e] = __half2float(h);
        lo[e] = f[e] - hi[e];
    }
    h01 = pack_hf2(hi[0], hi[1]); h23 = pack_hf2(hi[2], hi[3]);
    l01 = pack_hf2(lo[0], lo[1]); l23 = pack_hf2(lo[2], lo[3]);
}

__device__ __forceinline__ void cp16(unsigned dst, const void* src) {
    asm volatile("cp.async.cg.shared.global [%0], [%1], 16;\n" :: "r"(dst), "l"(src));
}
#define CP_COMMIT() asm volatile("cp.async.commit_group;\n")
#define CP_WAIT1()  asm volatile("cp.async.wait_group 1;\n")

// ---------------------------------------------------------------------------
// prep kernels
// ---------------------------------------------------------------------------
__global__ void splith_kernel(const float* __restrict__ src,
                              __half* __restrict__ h,
                              __half* __restrict__ l, int n4)
{
    int i = blockIdx.x * blockDim.x + threadIdx.x;
    if (i < n4) {
        float4 v = reinterpret_cast<const float4*>(src)[i];
        unsigned h01, h23, l01, l23;
        split4h(v, h01, h23, l01, l23);
        reinterpret_cast<unsigned*>(h)[i * 2]     = h01;
        reinterpret_cast<unsigned*>(h)[i * 2 + 1] = h23;
        reinterpret_cast<unsigned*>(l)[i * 2]     = l01;
        reinterpret_cast<unsigned*>(l)[i * 2 + 1] = l23;
    }
}

__global__ void tof16_kernel(const float* __restrict__ src,
                             __half* __restrict__ h, int n4)
{
    int i = blockIdx.x * blockDim.x + threadIdx.x;
    if (i < n4) {
        float4 v = reinterpret_cast<const float4*>(src)[i];
        reinterpret_cast<unsigned*>(h)[i * 2]     = pack_hf2(v.x, v.y);
        reinterpret_cast<unsigned*>(h)[i * 2 + 1] = pack_hf2(v.z, v.w);
    }
}

// ---------------------------------------------------------------------------
// fp16 2-term tensor-core GEMM: C = (Ah + Al) @ fp16(W) + bias  (== A @ Wh)
// Out: fp32 (splitOut=0) or split fp16 pair.
// ---------------------------------------------------------------------------
#define AP 40
#define WP 136
#define AS (128 * AP)
#define WS (32 * WP)
#define STG2 (2 * AS + WS)
#define GEMM_SMEM_BYTES (2 * STG2 * 2)

__global__ __launch_bounds__(256, 2) void gemm_f16_2t_kernel(
    const __half* __restrict__ Ahg, const __half* __restrict__ Alg,
    const __half* __restrict__ Whg,
    const float* __restrict__ bias,
    float* __restrict__ Cf,
    __half* __restrict__ Ch, __half* __restrict__ Cl,
    int M, int N, int K, int splitOut)
{
    extern __shared__ __half smg[];
    const unsigned sbase = (unsigned)__cvta_generic_to_shared(smg);

    const int t    = threadIdx.x;
    const int lane = t & 31;
    const int warp = t >> 5;
    const int g    = lane >> 2;
    const int tig  = lane & 3;
    const int wm   = warp >> 2;
    const int wn   = warp & 3;
    const int m0   = blockIdx.y << 7;
    const int n0   = blockIdx.x << 7;

    float acc[4][4][4];
#pragma unroll
    for (int i = 0; i < 4; i++)
#pragma unroll
        for (int j = 0; j < 4; j++)
#pragma unroll
            for (int r = 0; r < 4; r++) acc[i][j][r] = 0.f;

    auto issue = [&](int it, int stg) {
        const int k0 = it << 5;
        const unsigned base = sbase + (unsigned)(stg * STG2 * 2);
#pragma unroll
        for (int c = t; c < 512; c += 256) {
            const int row = c >> 2, off = (c & 3) << 3;
            const size_t s = (size_t)(m0 + row) * K + k0 + off;
            cp16(base + (unsigned)((row * AP + off) * 2), Ahg + s);
            cp16(base + (unsigned)((AS + row * AP + off) * 2), Alg + s);
        }
#pragma unroll
        for (int c = t; c < 512; c += 256) {
            const int row = c >> 4, off = (c & 15) << 3;
            const size_t s = (size_t)(k0 + row) * N + n0 + off;
            cp16(base + (unsigned)((2 * AS + row * WP + off) * 2), Whg + s);
        }
    };

    issue(0, 0);
    CP_COMMIT();

    const int NIT = K >> 5;
    for (int it = 0; it < NIT; it++) {
        if (it + 1 < NIT) issue(it + 1, (it + 1) & 1);
        CP_COMMIT();
        CP_WAIT1();
        __syncthreads();

        const unsigned ah_b = sbase + (unsigned)((it & 1) * STG2 * 2);
        const unsigned al_b = ah_b + AS * 2;
        const unsigned wh_b = ah_b + 2 * AS * 2;

#pragma unroll
        for (int kc = 0; kc < 32; kc += 16) {
            unsigned ahi[4][4], alo[4][4], bh[4][2];
#pragma unroll
            for (int mt = 0; mt < 4; mt++) {
                const int row = (wm << 6) + (mt << 4) + (lane & 15);
                const int col = kc + ((lane >> 4) << 3);
                const unsigned off = (unsigned)(row * (AP * 2) + col * 2);
                ldsm_x4(ahi[mt], ah_b + off);
                ldsm_x4(alo[mt], al_b + off);
            }
#pragma unroll
            for (int nt = 0; nt < 4; nt++) {
                const int krow = kc + (lane & 15);
                const int ncol = (wn << 5) + (nt << 3);
                const unsigned off = (unsigned)(krow * (WP * 2) + ncol * 2);
                ldsm_x2t(bh[nt], wh_b + off);
            }
#pragma unroll
            for (int mt = 0; mt < 4; mt++)
#pragma unroll
                for (int nt = 0; nt < 4; nt++)
                    mma_f16(acc[mt][nt], ahi[mt][0], ahi[mt][1], ahi[mt][2], ahi[mt][3],
                            bh[nt][0], bh[nt][1]);
#pragma unroll
            for (int mt = 0; mt < 4; mt++)
#pragma unroll
                for (int nt = 0; nt < 4; nt++)
                    mma_f16(acc[mt][nt], alo[mt][0], alo[mt][1], alo[mt][2], alo[mt][3],
                            bh[nt][0], bh[nt][1]);
        }
        __syncthreads();
    }

    // Epilogue
#pragma unroll
    for (int mt = 0; mt < 4; mt++) {
        const int row0 = m0 + (wm << 6) + (mt << 4) + g;
        const int row1 = row0 + 8;
#pragma unroll
        for (int nt = 0; nt < 4; nt++) {
            const int col = n0 + (wn << 5) + (nt << 3) + (tig << 1);
            const float b0 = bias[col];
            const float b1 = bias[col + 1];
            float v00 = acc[mt][nt][0] + b0, v01 = acc[mt][nt][1] + b1;
            float v10 = acc[mt][nt][2] + b0, v11 = acc[mt][nt][3] + b1;
            if (!splitOut) {
                float2 w0 = {v00, v01}, w1 = {v10, v11};
                *(float2*)(Cf + (size_t)row0 * N + col) = w0;
                *(float2*)(Cf + (size_t)row1 * N + col) = w1;
            } else {
                __half h00 = __float2half_rn(v00);
                __half h01 = __float2half_rn(v01);
                __half h10 = __float2half_rn(v10);
                __half h11 = __float2half_rn(v11);
                float l00 = v00 - __half2float(h00);
                float l01 = v01 - __half2float(h01);
                float l10 = v10 - __half2float(h10);
                float l11 = v11 - __half2float(h11);
                __half2 t0 = {h00, h01};
                __half2 t1 = {h10, h11};
                *reinterpret_cast<unsigned*>(Ch + (size_t)row0 * N + col) =
                    *reinterpret_cast<unsigned*>(&t0);
                *reinterpret_cast<unsigned*>(Ch + (size_t)row1 * N + col) =
                    *reinterpret_cast<unsigned*>(&t1);
                *reinterpret_cast<unsigned*>(Cl + (size_t)row0 * N + col) = pack_hf2(l00, l01);
                *reinterpret_cast<unsigned*>(Cl + (size_t)row1 * N + col) = pack_hf2(l10, l11);
            }
        }
    }
}

// ---------------------------------------------------------------------------
// Flash attention (causal), fp16 2-term MMA:
//   S = (Qh + Ql) @ Kh^T     (exact Q, K rounded to fp16)
//   O = (Ph + Pl) @ Vh       (exact P, V rounded to fp16)
// K,V load only the hi buffer; smem = 6 tiles instead of 8.
// ---------------------------------------------------------------------------
#define QP 72
#define ATT3_SMEM_BYTES (6 * 64 * QP * 2 + 64 * 68 * 4 + 3 * 64 * 4)

__global__ __launch_bounds__(256) void attn_mma_kernel(
    const __half* __restrict__ qkvh, const __half* __restrict__ qkvl,
    __half* __restrict__ zh, __half* __restrict__ zl)
{
    extern __shared__ char smraw[];
    __half* Qh = (__half*)smraw;
    __half* Ql = Qh + 64 * QP;
    __half* Kh = Ql + 64 * QP;
    __half* Vh = Kh + 64 * QP;
    __half* Ph = Vh + 64 * QP;
    __half* Pl = Ph + 64 * QP;
    float* Ss   = (float*)(Pl + 64 * QP);
    float* mrow = Ss + 64 * 68;
    float* lrow = mrow + 64;
    float* alph = lrow + 64;

    const int t    = threadIdx.x;
    const int lane = t & 31;
    const int warp = t >> 5;
    const int g    = lane >> 2;
    const int tig  = lane & 3;
    const int wm   = warp >> 1;
    const int wn   = warp & 1;
    const int qt   = (S_LEN / 64 - 1) - blockIdx.x;
    const int bh   = blockIdx.y;
    const int b    = bh >> 4;
    const int h    = bh & 15;

    const unsigned qh_b = (unsigned)__cvta_generic_to_shared(Qh);
    const unsigned ql_b = (unsigned)__cvta_generic_to_shared(Ql);
    const unsigned kh_b = (unsigned)__cvta_generic_to_shared(Kh);
    const unsigned vh_b = (unsigned)__cvta_generic_to_shared(Vh);
    const unsigned ph_b = (unsigned)__cvta_generic_to_shared(Ph);
    const unsigned pl_b = (unsigned)__cvta_generic_to_shared(Pl);

    const size_t rs = QKV_COLS;
    const size_t qoff = (size_t)(b * S_LEN + qt * 64) * rs + h * HD;

    // Load Q tile (fp16 hi/lo)
#pragma unroll
    for (int i = 0; i < 2; i++) {
        int idx = i * 256 + t;
        int r = idx >> 3, c8 = (idx & 7) << 3;
        float4 vh4 = *(const float4*)(qkvh + qoff + (size_t)r * rs + c8);
        float4 vl4 = *(const float4*)(qkvl + qoff + (size_t)r * rs + c8);
        *(float4*)&Qh[r * QP + c8] = vh4;
        *(float4*)&Ql[r * QP + c8] = vl4;
    }
    if (t < 64) { mrow[t] = -1e30f; lrow[t] = 0.f; }

    float o[4][4];
#pragma unroll
    for (int i = 0; i < 4; i++)
#pragma unroll
        for (int j = 0; j < 4; j++) o[i][j] = 0.f;

    for (int kt = 0; kt <= qt; kt++) {
        const size_t koff = (size_t)(b * S_LEN + kt * 64) * rs + D_MODEL + h * HD;
        const size_t voff = koff + D_MODEL;
        // K, V: hi buffer only
#pragma unroll
        for (int i = 0; i < 2; i++) {
            int idx = i * 256 + t;
            int r = idx >> 3, c8 = (idx & 7) << 3;
            float4 a = *(const float4*)(qkvh + koff + (size_t)r * rs + c8);
            float4 d = *(const float4*)(qkvh + voff + (size_t)r * rs + c8);
            *(float4*)&Kh[r * QP + c8] = a;
            *(float4*)&Vh[r * QP + c8] = d;
        }
        __syncthreads();

        // S = (Qh+Ql) K^T, 2 terms
        float sa[4][4];
#pragma unroll
        for (int i = 0; i < 4; i++)
#pragma unroll
            for (int j = 0; j < 4; j++) sa[i][j] = 0.f;

#pragma unroll
        for (int kc = 0; kc < 64; kc += 16) {
            unsigned aH[4], aL[4], bH[4][2];
            const unsigned aoff =
                (unsigned)(((wm << 4) + (lane & 15)) * (QP * 2) + (kc + ((lane >> 4) << 3)) * 2);
            ldsm_x4(aH, qh_b + aoff);
            ldsm_x4(aL, ql_b + aoff);
#pragma unroll
            for (int nt = 0; nt < 4; nt++) {
                const int nb = (wn << 5) + (nt << 3);
                const unsigned boff =
                    (unsigned)((nb + (lane & 7)) * (QP * 2) + (kc + (((lane >> 3) & 1) << 3)) * 2);
                ldsm_x2(bH[nt], kh_b + boff);
            }
#pragma unroll
            for (int nt = 0; nt < 4; nt++)
                mma_f16(sa[nt], aH[0], aH[1], aH[2], aH[3], bH[nt][0], bH[nt][1]);
#pragma unroll
            for (int nt = 0; nt < 4; nt++)
                mma_f16(sa[nt], aL[0], aL[1], aL[2], aL[3], bH[nt][0], bH[nt][1]);
        }

        {
            const bool diag = (kt == qt);
            const int r0l = (wm << 4) + g;
            const int r1l = r0l + 8;
#pragma unroll
            for (int nt = 0; nt < 4; nt++) {
                const int cb = (wn << 5) + (nt << 3) + (tig << 1);
                float v0 = sa[nt][0] * 0.125f;
                float v1 = sa[nt][1] * 0.125f;
                float v2 = sa[nt][2] * 0.125f;
                float v3 = sa[nt][3] * 0.125f;
                if (diag) {
                    if (cb     > r0l) v0 = -1e30f;
                    if (cb + 1 > r0l) v1 = -1e30f;
                    if (cb     > r1l) v2 = -1e30f;
                    if (cb + 1 > r1l) v3 = -1e30f;
                }
                float2 w0 = {v0, v1}, w1 = {v2, v3};
                *(float2*)&Ss[r0l * 68 + cb] = w0;
                *(float2*)&Ss[r1l * 68 + cb] = w1;
            }
        }
        __syncthreads();

        // online softmax, emit fp16 split P
        {
            const int r  = t >> 2;
            const int qq = t & 3;
            float* srow = &Ss[r * 68 + qq * 16];
            float4 v0 = *(float4*)&srow[0];
            float4 v1 = *(float4*)&srow[4];
            float4 v2 = *(float4*)&srow[8];
            float4 v3 = *(float4*)&srow[12];
            float mloc = fmaxf(fmaxf(fmaxf(v0.x, v0.y), fmaxf(v0.z, v0.w)),
                               fmaxf(fmaxf(v1.x, v1.y), fmaxf(v1.z, v1.w)));
            mloc = fmaxf(mloc, fmaxf(fmaxf(v2.x, v2.y), fmaxf(v2.z, v2.w)));
            mloc = fmaxf(mloc, fmaxf(fmaxf(v3.x, v3.y), fmaxf(v3.z, v3.w)));
            mloc = fmaxf(mloc, __shfl_xor_sync(0xffffffffu, mloc, 1));
            mloc = fmaxf(mloc, __shfl_xor_sync(0xffffffffu, mloc, 2));
            float mold = mrow[r];
            float mnew = fmaxf(mold, mloc);

            float p[16];
            p[0]  = __expf(v0.x - mnew); p[1]  = __expf(v0.y - mnew);
            p[2]  = __expf(v0.z - mnew); p[3]  = __expf(v0.w - mnew);
            p[4]  = __expf(v1.x - mnew); p[5]  = __expf(v1.y - mnew);
            p[6]  = __expf(v1.z - mnew); p[7]  = __expf(v1.w - mnew);
            p[8]  = __expf(v2.x - mnew); p[9]  = __expf(v2.y - mnew);
            p[10] = __expf(v2.z - mnew); p[11] = __expf(v2.w - mnew);
            p[12] = __expf(v3.x - mnew); p[13] = __expf(v3.y - mnew);
            p[14] = __expf(v3.z - mnew); p[15] = __expf(v3.w - mnew);

            float lsum = 0.f;
#pragma unroll
            for (int e = 0; e < 16; e++) lsum += p[e];

            const int cbase = r * QP + qq * 16;
#pragma unroll
            for (int e = 0; e < 16; e += 4) {
                float4 pv = {p[e], p[e + 1], p[e + 2], p[e + 3]};
                unsigned h01, h23, l01, l23;
                split4h(pv, h01, h23, l01, l23);
                *reinterpret_cast<unsigned*>(&Ph[cbase + e])     = h01;
                *reinterpret_cast<unsigned*>(&Ph[cbase + e + 2]) = h23;
                *reinterpret_cast<unsigned*>(&Pl[cbase + e])     = l01;
                *reinterpret_cast<unsigned*>(&Pl[cbase + e + 2]) = l23;
            }

            lsum += __shfl_xor_sync(0xffffffffu, lsum, 1);
            lsum += __shfl_xor_sync(0xffffffffu, lsum, 2);
            if (qq == 0) {
                float alpha = __expf(mold - mnew);
                lrow[r] = lrow[r] * alpha + lsum;
                mrow[r] = mnew;
                alph[r] = alpha;
            }
        }
        __syncthreads();

        // O = O*alpha + (Ph+Pl) V, 2 terms
        {
            const float a0 = alph[(wm << 4) + g];
            const float a1 = alph[(wm << 4) + g + 8];
#pragma unroll
            for (int nt = 0; nt < 4; nt++) {
                o[nt][0] *= a0; o[nt][1] *= a0;
                o[nt][2] *= a1; o[nt][3] *= a1;
            }
#pragma unroll
            for (int kc = 0; kc < 64; kc += 16) {
                unsigned pH[4], pL[4], vH[4][2];
                const unsigned poff =
                    (unsigned)(((wm << 4) + (lane & 15)) * (QP * 2) + (kc + ((lane >> 4) << 3)) * 2);
                ldsm_x4(pH, ph_b + poff);
                ldsm_x4(pL, pl_b + poff);
#pragma unroll
                for (int nt = 0; nt < 4; nt++) {
                    const int nb = (wn << 5) + (nt << 3);
                    const unsigned voff2 =
                        (unsigned)((kc + (lane & 15)) * (QP * 2) + nb * 2);
                    ldsm_x2t(vH[nt], vh_b + voff2);
                }
#pragma unroll
                for (int nt = 0; nt < 4; nt++)
                    mma_f16(o[nt], pH[0], pH[1], pH[2], pH[3], vH[nt][0], vH[nt][1]);
#pragma unroll
                for (int nt = 0; nt < 4; nt++)
                    mma_f16(o[nt], pL[0], pL[1], pL[2], pL[3], vH[nt][0], vH[nt][1]);
            }
        }
        __syncthreads();
    }

    // Epilogue: divide by l, write fp16 split z
    {
        const float l0 = 1.f / lrow[(wm << 4) + g];
        const float l1 = 1.f / lrow[(wm << 4) + g + 8];
        const int row0 = qt * 64 + (wm << 4) + g;
        const int row1 = row0 + 8;
#pragma unroll
        for (int nt = 0; nt < 4; nt++) {
            const int col = (wn << 5) + (nt << 3) + (tig << 1);
            float w00 = o[nt][0] * l0, w01 = o[nt][1] * l0;
            float w10 = o[nt][2] * l1, w11 = o[nt][3] * l1;
            __half h00 = __float2half_rn(w00);
            __half h01 = __float2half_rn(w01);
            __half h10 = __float2half_rn(w10);
            __half h11 = __float2half_rn(w11);
            float l00 = w00 - __half2float(h00);
            float l01v = w01 - __half2float(h01);
            float l10 = w10 - __half2float(h10);
            float l11 = w11 - __half2float(h11);
            size_t o0 = (size_t)(b * S_LEN + row0) * D_MODEL + h * HD + col;
            size_t o1 = (size_t)(b * S_LEN + row1) * D_MODEL + h * HD + col;
            __half2 t0 = {h00, h01};
            __half2 t1 = {h10, h11};
            *reinterpret_cast<unsigned*>(zh + o0) = *reinterpret_cast<unsigned*>(&t0);
            *reinterpret_cast<unsigned*>(zh + o1) = *reinterpret_cast<unsigned*>(&t1);
            *reinterpret_cast<unsigned*>(zl + o0) = pack_hf2(l00, l01v);
            *reinterpret_cast<unsigned*>(zl + o1) = pack_hf2(l10, l11);
        }
    }
}

// ---------------------------------------------------------------------------
extern "C" void kernel_launch(void* const* d_in, const int* in_sizes, int n_in,
                              void* d_out, int out_size)
{
    const float* x     = (const float*)d_in[0];
    const float* w_qkv = (const float*)d_in[1];
    const float* b_qkv = (const float*)d_in[2];
    const float* w_out = (const float*)d_in[3];
    const float* b_out = (const float*)d_in[4];
    float* out = (float*)d_out;

    __half *xh, *xl, *wqh, *woh, *qkvh, *qkvl, *zh, *zl;
    cudaGetSymbolAddress((void**)&xh, g_xh);
    cudaGetSymbolAddress((void**)&xl, g_xl);
    cudaGetSymbolAddress((void**)&wqh, g_wqh);
    cudaGetSymbolAddress((void**)&woh, g_woh);
    cudaGetSymbolAddress((void**)&qkvh, g_qkvh);
    cudaGetSymbolAddress((void**)&qkvl, g_qkvl);
    cudaGetSymbolAddress((void**)&zh, g_zh);
    cudaGetSymbolAddress((void**)&zl, g_zl);

    cudaFuncSetAttribute(gemm_f16_2t_kernel,
                         cudaFuncAttributeMaxDynamicSharedMemorySize,
                         GEMM_SMEM_BYTES);
    cudaFuncSetAttribute(attn_mma_kernel,
                         cudaFuncAttributeMaxDynamicSharedMemorySize,
                         ATT3_SMEM_BYTES);

    // 0) split x to fp16 hi/lo; convert weights to fp16
    {
        int n;
        n = M_ROWS * D_MODEL / 4;
        splith_kernel<<<(n + 255) / 256, 256>>>(x, xh, xl, n);
        n = D_MODEL * QKV_COLS / 4;
        tof16_kernel<<<(n + 255) / 256, 256>>>(w_qkv, wqh, n);
        n = D_MODEL * D_MODEL / 4;
        tof16_kernel<<<(n + 255) / 256, 256>>>(w_out, woh, n);
    }
    // 1) QKV GEMM (fp16 2-term) -> fp16 split qkv
    {
        dim3 grid(QKV_COLS / 128, M_ROWS / 128);
        gemm_f16_2t_kernel<<<grid, 256, GEMM_SMEM_BYTES>>>(
            xh, xl, wqh, b_qkv, nullptr, qkvh, qkvl,
            M_ROWS, QKV_COLS, D_MODEL, 1);
    }
    // 2) attention (fp16 2-term) -> fp16 split z
    {
        dim3 grid(S_LEN / 64, B_SZ * NH);
        attn_mma_kernel<<<grid, 256, ATT3_SMEM_BYTES>>>(qkvh, qkvl, zh, zl);
    }
    // 3) out GEMM (fp16 2-term) -> fp32 output
    {
        dim3 grid(D_MODEL / 128, M_ROWS / 128);
        gemm_f16_2t_kernel<<<grid, 256, GEMM_SMEM_BYTES>>>(
            zh, zl, woh, b_out, out, nullptr, nullptr,
            M_ROWS, D_MODEL, D_MODEL, 0);
    }
}

// round 17
// speedup vs baseline: 4.4424x; 1.3608x over previous
#include <cuda_runtime.h>
#include <cuda_bf16.h>
#include <cuda_fp16.h>
#include <math.h>

#define S_LEN 2048
#define B_SZ 2
#define D_MODEL 1024
#define NH 16
#define HD 64
#define M_ROWS 4096
#define QKV_COLS 3072

// fp16 buffers
__device__ __half g_xh[(size_t)M_ROWS * D_MODEL];
__device__ __half g_wqh[(size_t)D_MODEL * QKV_COLS];
__device__ __half g_woh[(size_t)D_MODEL * D_MODEL];
__device__ __half g_qkvh[(size_t)M_ROWS * QKV_COLS];
__device__ __half g_qkvl[(size_t)M_ROWS * QKV_COLS];
__device__ __half g_zh[(size_t)M_ROWS * D_MODEL];

// ---------------------------------------------------------------------------
// helpers
// ---------------------------------------------------------------------------
__device__ __forceinline__ unsigned pack_hf2(float x, float y) {
    __half2 h = __floats2half2_rn(x, y);
    return *reinterpret_cast<unsigned*>(&h);
}

__device__ __forceinline__ void mma_f16(float* c,
                                        unsigned a0, unsigned a1,
                                        unsigned a2, unsigned a3,
                                        unsigned b0, unsigned b1) {
    asm volatile(
        "mma.sync.aligned.m16n8k16.row.col.f32.f16.f16.f32 "
        "{%0,%1,%2,%3}, {%4,%5,%6,%7}, {%8,%9}, {%0,%1,%2,%3};\n"
        : "+f"(c[0]), "+f"(c[1]), "+f"(c[2]), "+f"(c[3])
        : "r"(a0), "r"(a1), "r"(a2), "r"(a3), "r"(b0), "r"(b1));
}

__device__ __forceinline__ void ldsm_x4(unsigned r[4], unsigned addr) {
    asm volatile("ldmatrix.sync.aligned.m8n8.x4.shared.b16 {%0,%1,%2,%3}, [%4];"
                 : "=r"(r[0]), "=r"(r[1]), "=r"(r[2]), "=r"(r[3]) : "r"(addr));
}
__device__ __forceinline__ void ldsm_x2(unsigned r[2], unsigned addr) {
    asm volatile("ldmatrix.sync.aligned.m8n8.x2.shared.b16 {%0,%1}, [%2];"
                 : "=r"(r[0]), "=r"(r[1]) : "r"(addr));
}
__device__ __forceinline__ void ldsm_x2t(unsigned r[2], unsigned addr) {
    asm volatile("ldmatrix.sync.aligned.m8n8.x2.trans.shared.b16 {%0,%1}, [%2];"
                 : "=r"(r[0]), "=r"(r[1]) : "r"(addr));
}

// fp16 hi/lo split of a float4
__device__ __forceinline__ void split4h(float4 v,
                                        unsigned& h01, unsigned& h23,
                                        unsigned& l01, unsigned& l23) {
    float f[4] = {v.x, v.y, v.z, v.w};
    float hi[4], lo[4];
#pragma unroll
    for (int e = 0; e < 4; e++) {
        __half h = __float2half_rn(f[e]);
        hi[e] = __half2float(h);
        lo[e] = f[e] - hi[e];
    }
    h01 = pack_hf2(hi[0], hi[1]); h23 = pack_hf2(hi[2], hi[3]);
    l01 = pack_hf2(lo[0], lo[1]); l23 = pack_hf2(lo[2], lo[3]);
}

__device__ __forceinline__ void cp16(unsigned dst, const void* src) {
    asm volatile("cp.async.cg.shared.global [%0], [%1], 16;\n" :: "r"(dst), "l"(src));
}
#define CP_COMMIT() asm volatile("cp.async.commit_group;\n")
#define CP_WAIT1()  asm volatile("cp.async.wait_group 1;\n")

// ---------------------------------------------------------------------------
// prep: fp32 -> fp16
// ---------------------------------------------------------------------------
__global__ void tof16_kernel(const float* __restrict__ src,
                             __half* __restrict__ h, int n4)
{
    int i = blockIdx.x * blockDim.x + threadIdx.x;
    if (i < n4) {
        float4 v = reinterpret_cast<const float4*>(src)[i];
        reinterpret_cast<unsigned*>(h)[i * 2]     = pack_hf2(v.x, v.y);
        reinterpret_cast<unsigned*>(h)[i * 2 + 1] = pack_hf2(v.z, v.w);
    }
}

// ---------------------------------------------------------------------------
// Plain fp16 tensor-core GEMM: C = fp16(A) @ fp16(W) + bias
// BM=BN=128, BK=32, 8 warps (2x4), warp tile 64x32, m16n8k16, cp.async 2-stage.
// Out: fp32 (splitOut=0) or split fp16 pair (for attention Q exactness).
// ---------------------------------------------------------------------------
#define AP 40
#define WP 136
#define AS (128 * AP)
#define WS (32 * WP)
#define STG1 (AS + WS)
#define GEMM_SMEM_BYTES (2 * STG1 * 2)

__global__ __launch_bounds__(256, 2) void gemm_f16_kernel(
    const __half* __restrict__ Ahg,
    const __half* __restrict__ Whg,
    const float* __restrict__ bias,
    float* __restrict__ Cf,
    __half* __restrict__ Ch, __half* __restrict__ Cl,
    int M, int N, int K, int splitOut)
{
    extern __shared__ __half smg[];
    const unsigned sbase = (unsigned)__cvta_generic_to_shared(smg);

    const int t    = threadIdx.x;
    const int lane = t & 31;
    const int warp = t >> 5;
    const int g    = lane >> 2;
    const int tig  = lane & 3;
    const int wm   = warp >> 2;
    const int wn   = warp & 3;
    const int m0   = blockIdx.y << 7;
    const int n0   = blockIdx.x << 7;

    float acc[4][4][4];
#pragma unroll
    for (int i = 0; i < 4; i++)
#pragma unroll
        for (int j = 0; j < 4; j++)
#pragma unroll
            for (int r = 0; r < 4; r++) acc[i][j][r] = 0.f;

    auto issue = [&](int it, int stg) {
        const int k0 = it << 5;
        const unsigned base = sbase + (unsigned)(stg * STG1 * 2);
#pragma unroll
        for (int c = t; c < 512; c += 256) {
            const int row = c >> 2, off = (c & 3) << 3;
            const size_t s = (size_t)(m0 + row) * K + k0 + off;
            cp16(base + (unsigned)((row * AP + off) * 2), Ahg + s);
        }
#pragma unroll
        for (int c = t; c < 512; c += 256) {
            const int row = c >> 4, off = (c & 15) << 3;
            const size_t s = (size_t)(k0 + row) * N + n0 + off;
            cp16(base + (unsigned)((AS + row * WP + off) * 2), Whg + s);
        }
    };

    issue(0, 0);
    CP_COMMIT();

    const int NIT = K >> 5;
    for (int it = 0; it < NIT; it++) {
        if (it + 1 < NIT) issue(it + 1, (it + 1) & 1);
        CP_COMMIT();
        CP_WAIT1();
        __syncthreads();

        const unsigned ah_b = sbase + (unsigned)((it & 1) * STG1 * 2);
        const unsigned wh_b = ah_b + AS * 2;

#pragma unroll
        for (int kc = 0; kc < 32; kc += 16) {
            unsigned ahi[4][4], bh[4][2];
#pragma unroll
            for (int mt = 0; mt < 4; mt++) {
                const int row = (wm << 6) + (mt << 4) + (lane & 15);
                const int col = kc + ((lane >> 4) << 3);
                const unsigned off = (unsigned)(row * (AP * 2) + col * 2);
                ldsm_x4(ahi[mt], ah_b + off);
            }
#pragma unroll
            for (int nt = 0; nt < 4; nt++) {
                const int krow = kc + (lane & 15);
                const int ncol = (wn << 5) + (nt << 3);
                const unsigned off = (unsigned)(krow * (WP * 2) + ncol * 2);
                ldsm_x2t(bh[nt], wh_b + off);
            }
#pragma unroll
            for (int mt = 0; mt < 4; mt++)
#pragma unroll
                for (int nt = 0; nt < 4; nt++)
                    mma_f16(acc[mt][nt], ahi[mt][0], ahi[mt][1], ahi[mt][2], ahi[mt][3],
                            bh[nt][0], bh[nt][1]);
        }
        __syncthreads();
    }

    // Epilogue
#pragma unroll
    for (int mt = 0; mt < 4; mt++) {
        const int row0 = m0 + (wm << 6) + (mt << 4) + g;
        const int row1 = row0 + 8;
#pragma unroll
        for (int nt = 0; nt < 4; nt++) {
            const int col = n0 + (wn << 5) + (nt << 3) + (tig << 1);
            const float b0 = bias[col];
            const float b1 = bias[col + 1];
            float v00 = acc[mt][nt][0] + b0, v01 = acc[mt][nt][1] + b1;
            float v10 = acc[mt][nt][2] + b0, v11 = acc[mt][nt][3] + b1;
            if (!splitOut) {
                float2 w0 = {v00, v01}, w1 = {v10, v11};
                *(float2*)(Cf + (size_t)row0 * N + col) = w0;
                *(float2*)(Cf + (size_t)row1 * N + col) = w1;
            } else {
                __half h00 = __float2half_rn(v00);
                __half h01 = __float2half_rn(v01);
                __half h10 = __float2half_rn(v10);
                __half h11 = __float2half_rn(v11);
                float l00 = v00 - __half2float(h00);
                float l01 = v01 - __half2float(h01);
                float l10 = v10 - __half2float(h10);
                float l11 = v11 - __half2float(h11);
                __half2 t0 = {h00, h01};
                __half2 t1 = {h10, h11};
                *reinterpret_cast<unsigned*>(Ch + (size_t)row0 * N + col) =
                    *reinterpret_cast<unsigned*>(&t0);
                *reinterpret_cast<unsigned*>(Ch + (size_t)row1 * N + col) =
                    *reinterpret_cast<unsigned*>(&t1);
                *reinterpret_cast<unsigned*>(Cl + (size_t)row0 * N + col) = pack_hf2(l00, l01);
                *reinterpret_cast<unsigned*>(Cl + (size_t)row1 * N + col) = pack_hf2(l10, l11);
            }
        }
    }
}

// ---------------------------------------------------------------------------
// Flash attention (causal), fp16 2-term MMA (unchanged math, verified):
//   S = (Qh + Ql) @ Kh^T ;  O = (Ph + Pl) @ Vh.  Emits zh only.
// ---------------------------------------------------------------------------
#define QP 72
#define ATT3_SMEM_BYTES (6 * 64 * QP * 2 + 64 * 68 * 4 + 3 * 64 * 4)

__global__ __launch_bounds__(256) void attn_mma_kernel(
    const __half* __restrict__ qkvh, const __half* __restrict__ qkvl,
    __half* __restrict__ zh)
{
    extern __shared__ char smraw[];
    __half* Qh = (__half*)smraw;
    __half* Ql = Qh + 64 * QP;
    __half* Kh = Ql + 64 * QP;
    __half* Vh = Kh + 64 * QP;
    __half* Ph = Vh + 64 * QP;
    __half* Pl = Ph + 64 * QP;
    float* Ss   = (float*)(Pl + 64 * QP);
    float* mrow = Ss + 64 * 68;
    float* lrow = mrow + 64;
    float* alph = lrow + 64;

    const int t    = threadIdx.x;
    const int lane = t & 31;
    const int warp = t >> 5;
    const int g    = lane >> 2;
    const int tig  = lane & 3;
    const int wm   = warp >> 1;
    const int wn   = warp & 1;
    const int qt   = (S_LEN / 64 - 1) - blockIdx.x;
    const int bh   = blockIdx.y;
    const int b    = bh >> 4;
    const int h    = bh & 15;

    const unsigned qh_b = (unsigned)__cvta_generic_to_shared(Qh);
    const unsigned ql_b = (unsigned)__cvta_generic_to_shared(Ql);
    const unsigned kh_b = (unsigned)__cvta_generic_to_shared(Kh);
    const unsigned vh_b = (unsigned)__cvta_generic_to_shared(Vh);
    const unsigned ph_b = (unsigned)__cvta_generic_to_shared(Ph);
    const unsigned pl_b = (unsigned)__cvta_generic_to_shared(Pl);

    const size_t rs = QKV_COLS;
    const size_t qoff = (size_t)(b * S_LEN + qt * 64) * rs + h * HD;

#pragma unroll
    for (int i = 0; i < 2; i++) {
        int idx = i * 256 + t;
        int r = idx >> 3, c8 = (idx & 7) << 3;
        float4 vh4 = *(const float4*)(qkvh + qoff + (size_t)r * rs + c8);
        float4 vl4 = *(const float4*)(qkvl + qoff + (size_t)r * rs + c8);
        *(float4*)&Qh[r * QP + c8] = vh4;
        *(float4*)&Ql[r * QP + c8] = vl4;
    }
    if (t < 64) { mrow[t] = -1e30f; lrow[t] = 0.f; }

    float o[4][4];
#pragma unroll
    for (int i = 0; i < 4; i++)
#pragma unroll
        for (int j = 0; j < 4; j++) o[i][j] = 0.f;

    for (int kt = 0; kt <= qt; kt++) {
        const size_t koff = (size_t)(b * S_LEN + kt * 64) * rs + D_MODEL + h * HD;
        const size_t voff = koff + D_MODEL;
#pragma unroll
        for (int i = 0; i < 2; i++) {
            int idx = i * 256 + t;
            int r = idx >> 3, c8 = (idx & 7) << 3;
            float4 a = *(const float4*)(qkvh + koff + (size_t)r * rs + c8);
            float4 d = *(const float4*)(qkvh + voff + (size_t)r * rs + c8);
            *(float4*)&Kh[r * QP + c8] = a;
            *(float4*)&Vh[r * QP + c8] = d;
        }
        __syncthreads();

        float sa[4][4];
#pragma unroll
        for (int i = 0; i < 4; i++)
#pragma unroll
            for (int j = 0; j < 4; j++) sa[i][j] = 0.f;

#pragma unroll
        for (int kc = 0; kc < 64; kc += 16) {
            unsigned aH[4], aL[4], bH[4][2];
            const unsigned aoff =
                (unsigned)(((wm << 4) + (lane & 15)) * (QP * 2) + (kc + ((lane >> 4) << 3)) * 2);
            ldsm_x4(aH, qh_b + aoff);
            ldsm_x4(aL, ql_b + aoff);
#pragma unroll
            for (int nt = 0; nt < 4; nt++) {
                const int nb = (wn << 5) + (nt << 3);
                const unsigned boff =
                    (unsigned)((nb + (lane & 7)) * (QP * 2) + (kc + (((lane >> 3) & 1) << 3)) * 2);
                ldsm_x2(bH[nt], kh_b + boff);
            }
#pragma unroll
            for (int nt = 0; nt < 4; nt++)
                mma_f16(sa[nt], aH[0], aH[1], aH[2], aH[3], bH[nt][0], bH[nt][1]);
#pragma unroll
            for (int nt = 0; nt < 4; nt++)
                mma_f16(sa[nt], aL[0], aL[1], aL[2], aL[3], bH[nt][0], bH[nt][1]);
        }

        {
            const bool diag = (kt == qt);
            const int r0l = (wm << 4) + g;
            const int r1l = r0l + 8;
#pragma unroll
            for (int nt = 0; nt < 4; nt++) {
                const int cb = (wn << 5) + (nt << 3) + (tig << 1);
                float v0 = sa[nt][0] * 0.125f;
                float v1 = sa[nt][1] * 0.125f;
                float v2 = sa[nt][2] * 0.125f;
                float v3 = sa[nt][3] * 0.125f;
                if (diag) {
                    if (cb     > r0l) v0 = -1e30f;
                    if (cb + 1 > r0l) v1 = -1e30f;
                    if (cb     > r1l) v2 = -1e30f;
                    if (cb + 1 > r1l) v3 = -1e30f;
                }
                float2 w0 = {v0, v1}, w1 = {v2, v3};
                *(float2*)&Ss[r0l * 68 + cb] = w0;
                *(float2*)&Ss[r1l * 68 + cb] = w1;
            }
        }
        __syncthreads();

        {
            const int r  = t >> 2;
            const int qq = t & 3;
            float* srow = &Ss[r * 68 + qq * 16];
            float4 v0 = *(float4*)&srow[0];
            float4 v1 = *(float4*)&srow[4];
            float4 v2 = *(float4*)&srow[8];
            float4 v3 = *(float4*)&srow[12];
            float mloc = fmaxf(fmaxf(fmaxf(v0.x, v0.y), fmaxf(v0.z, v0.w)),
                               fmaxf(fmaxf(v1.x, v1.y), fmaxf(v1.z, v1.w)));
            mloc = fmaxf(mloc, fmaxf(fmaxf(v2.x, v2.y), fmaxf(v2.z, v2.w)));
            mloc = fmaxf(mloc, fmaxf(fmaxf(v3.x, v3.y), fmaxf(v3.z, v3.w)));
            mloc = fmaxf(mloc, __shfl_xor_sync(0xffffffffu, mloc, 1));
            mloc = fmaxf(mloc, __shfl_xor_sync(0xffffffffu, mloc, 2));
            float mold = mrow[r];
            float mnew = fmaxf(mold, mloc);

            float p[16];
            p[0]  = __expf(v0.x - mnew); p[1]  = __expf(v0.y - mnew);
            p[2]  = __expf(v0.z - mnew); p[3]  = __expf(v0.w - mnew);
            p[4]  = __expf(v1.x - mnew); p[5]  = __expf(v1.y - mnew);
            p[6]  = __expf(v1.z - mnew); p[7]  = __expf(v1.w - mnew);
            p[8]  = __expf(v2.x - mnew); p[9]  = __expf(v2.y - mnew);
            p[10] = __expf(v2.z - mnew); p[11] = __expf(v2.w - mnew);
            p[12] = __expf(v3.x - mnew); p[13] = __expf(v3.y - mnew);
            p[14] = __expf(v3.z - mnew); p[15] = __expf(v3.w - mnew);

            float lsum = 0.f;
#pragma unroll
            for (int e = 0; e < 16; e++) lsum += p[e];

            const int cbase = r * QP + qq * 16;
#pragma unroll
            for (int e = 0; e < 16; e += 4) {
                float4 pv = {p[e], p[e + 1], p[e + 2], p[e + 3]};
                unsigned h01, h23, l01, l23;
                split4h(pv, h01, h23, l01, l23);
                *reinterpret_cast<unsigned*>(&Ph[cbase + e])     = h01;
                *reinterpret_cast<unsigned*>(&Ph[cbase + e + 2]) = h23;
                *reinterpret_cast<unsigned*>(&Pl[cbase + e])     = l01;
                *reinterpret_cast<unsigned*>(&Pl[cbase + e + 2]) = l23;
            }

            lsum += __shfl_xor_sync(0xffffffffu, lsum, 1);
            lsum += __shfl_xor_sync(0xffffffffu, lsum, 2);
            if (qq == 0) {
                float alpha = __expf(mold - mnew);
                lrow[r] = lrow[r] * alpha + lsum;
                mrow[r] = mnew;
                alph[r] = alpha;
            }
        }
        __syncthreads();

        {
            const float a0 = alph[(wm << 4) + g];
            const float a1 = alph[(wm << 4) + g + 8];
#pragma unroll
            for (int nt = 0; nt < 4; nt++) {
                o[nt][0] *= a0; o[nt][1] *= a0;
                o[nt][2] *= a1; o[nt][3] *= a1;
            }
#pragma unroll
            for (int kc = 0; kc < 64; kc += 16) {
                unsigned pH[4], pL[4], vH[4][2];
                const unsigned poff =
                    (unsigned)(((wm << 4) + (lane & 15)) * (QP * 2) + (kc + ((lane >> 4) << 3)) * 2);
                ldsm_x4(pH, ph_b + poff);
                ldsm_x4(pL, pl_b + poff);
#pragma unroll
                for (int nt = 0; nt < 4; nt++) {
                    const int nb = (wn << 5) + (nt << 3);
                    const unsigned voff2 =
                        (unsigned)((kc + (lane & 15)) * (QP * 2) + nb * 2);
                    ldsm_x2t(vH[nt], vh_b + voff2);
                }
#pragma unroll
                for (int nt = 0; nt < 4; nt++)
                    mma_f16(o[nt], pH[0], pH[1], pH[2], pH[3], vH[nt][0], vH[nt][1]);
#pragma unroll
                for (int nt = 0; nt < 4; nt++)
                    mma_f16(o[nt], pL[0], pL[1], pL[2], pL[3], vH[nt][0], vH[nt][1]);
            }
        }
        __syncthreads();
    }

    // Epilogue: divide by l, write fp16 zh only
    {
        const float l0 = 1.f / lrow[(wm << 4) + g];
        const float l1 = 1.f / lrow[(wm << 4) + g + 8];
        const int row0 = qt * 64 + (wm << 4) + g;
        const int row1 = row0 + 8;
#pragma unroll
        for (int nt = 0; nt < 4; nt++) {
            const int col = (wn << 5) + (nt << 3) + (tig << 1);
            float w00 = o[nt][0] * l0, w01 = o[nt][1] * l0;
            float w10 = o[nt][2] * l1, w11 = o[nt][3] * l1;
            size_t o0 = (size_t)(b * S_LEN + row0) * D_MODEL + h * HD + col;
            size_t o1 = (size_t)(b * S_LEN + row1) * D_MODEL + h * HD + col;
            *reinterpret_cast<unsigned*>(zh + o0) = pack_hf2(w00, w01);
            *reinterpret_cast<unsigned*>(zh + o1) = pack_hf2(w10, w11);
        }
    }
}

// ---------------------------------------------------------------------------
extern "C" void kernel_launch(void* const* d_in, const int* in_sizes, int n_in,
                              void* d_out, int out_size)
{
    const float* x     = (const float*)d_in[0];
    const float* w_qkv = (const float*)d_in[1];
    const float* b_qkv = (const float*)d_in[2];
    const float* w_out = (const float*)d_in[3];
    const float* b_out = (const float*)d_in[4];
    float* out = (float*)d_out;

    __half *xh, *wqh, *woh, *qkvh, *qkvl, *zh;
    cudaGetSymbolAddress((void**)&xh, g_xh);
    cudaGetSymbolAddress((void**)&wqh, g_wqh);
    cudaGetSymbolAddress((void**)&woh, g_woh);
    cudaGetSymbolAddress((void**)&qkvh, g_qkvh);
    cudaGetSymbolAddress((void**)&qkvl, g_qkvl);
    cudaGetSymbolAddress((void**)&zh, g_zh);

    cudaFuncSetAttribute(gemm_f16_kernel,
                         cudaFuncAttributeMaxDynamicSharedMemorySize,
                         GEMM_SMEM_BYTES);
    cudaFuncSetAttribute(attn_mma_kernel,
                         cudaFuncAttributeMaxDynamicSharedMemorySize,
                         ATT3_SMEM_BYTES);

    // 0) convert x and weights to fp16
    {
        int n;
        n = M_ROWS * D_MODEL / 4;
        tof16_kernel<<<(n + 255) / 256, 256>>>(x, xh, n);
        n = D_MODEL * QKV_COLS / 4;
        tof16_kernel<<<(n + 255) / 256, 256>>>(w_qkv, wqh, n);
        n = D_MODEL * D_MODEL / 4;
        tof16_kernel<<<(n + 255) / 256, 256>>>(w_out, woh, n);
    }
    // 1) QKV GEMM (fp16) -> fp16 split qkv (hi/lo for attention Q exactness)
    {
        dim3 grid(QKV_COLS / 128, M_ROWS / 128);
        gemm_f16_kernel<<<grid, 256, GEMM_SMEM_BYTES>>>(
            xh, wqh, b_qkv, nullptr, qkvh, qkvl,
            M_ROWS, QKV_COLS, D_MODEL, 1);
    }
    // 2) attention (fp16 2-term) -> fp16 zh
    {
        dim3 grid(S_LEN / 64, B_SZ * NH);
        attn_mma_kernel<<<grid, 256, ATT3_SMEM_BYTES>>>(qkvh, qkvl, zh);
    }
    // 3) out GEMM (fp16) -> fp32 output
    {
        dim3 grid(D_MODEL / 128, M_ROWS / 128);
        gemm_f16_kernel<<<grid, 256, GEMM_SMEM_BYTES>>>(
            zh, woh, b_out, out, nullptr, nullptr,
            M_ROWS, D_MODEL, D_MODEL, 0);
    }
}